// round 13
// baseline (speedup 1.0000x reference)
#include <cuda_runtime.h>
#include <cuda_bf16.h>
#include <cuda_fp16.h>
#include <cstdint>

// Problem constants
#define BB 4
#define CC 64
#define NN 4096
#define C8V 8
#define NIMG 8
#define NCHUNK 32
#define KSPL 8
#define NTILE (NN / KSPL / 128)
#define RLN2 1.4426950408889634f

// ---------------- scratch ----------------------------------------------------
__device__ float g_gpart[NCHUNK * NIMG * CC * CC];
__device__ float g_WqT[BB * CC * C8V];             // [b][c][o], prescaled by 1/ln2
__device__ float g_WkT[BB * CC * C8V];             // [b][c][o]
__device__ float g_WvTe[BB * CC * CC];             // [b][c][o]
__device__ __nv_bfloat16 g_qb[BB * NN * C8V];      // [b][n][8] (prescaled 1/ln2)
__device__ __nv_bfloat16 g_kb[BB * NN * C8V];      // [b][n][8]
__device__ __half        g_v [BB * NN * CC];       // [b][n][c]
__device__ uint32_t g_pDh[BB * KSPL * (CC / 2) * NN];  // packed f16x2 partials [b][s][cp][q]
__device__ float g_pl[BB * KSPL * NN];             // partial row-sums [b][s][q]

__device__ __forceinline__ uint32_t smem_u32(const void* p) {
    uint32_t a;
    asm("{ .reg .u64 t; cvta.to.shared.u64 t, %1; cvt.u32.u64 %0, t; }" : "=r"(a) : "l"(p));
    return a;
}

#define MMA_BF16_K8(d, a0, a1, b0)                                                 \
    asm volatile("mma.sync.aligned.m16n8k8.row.col.f32.bf16.bf16.f32 "             \
        "{%0,%1,%2,%3}, {%4,%5}, {%6}, {%0,%1,%2,%3};"                             \
        : "+f"((d)[0]), "+f"((d)[1]), "+f"((d)[2]), "+f"((d)[3])                   \
        : "r"(a0), "r"(a1), "r"(b0))

// fp16-accumulate MMA: D/C are 2 packed f16x2 regs
#define MMA_F16_H(d, a0, a1, a2, a3, b0, b1)                                       \
    asm volatile("mma.sync.aligned.m16n8k16.row.col.f16.f16.f16.f16 "              \
        "{%0,%1}, {%2,%3,%4,%5}, {%6,%7}, {%0,%1};"                                \
        : "+r"((d)[0]), "+r"((d)[1])                                               \
        : "r"(a0), "r"(a1), "r"(a2), "r"(a3), "r"(b0), "r"(b1))

#define CP16(dst, src) asm volatile("cp.async.cg.shared.global [%0], [%1], 16;" :: "r"(dst), "l"(src) : "memory")
#define CP_COMMIT()    asm volatile("cp.async.commit_group;" ::: "memory")

// ---------------- Stage A1: gram partials (4x4 register tiles) -----------------
__global__ void k_gram(const float* __restrict__ cnn, const float* __restrict__ vit) {
    int chunk = blockIdx.x, img = blockIdx.y;
    const float* x = (img < BB) ? (cnn + img * CC * NN) : (vit + (img - BB) * CC * NN);
    __shared__ float xs[CC][132];
    int n0 = chunk * 128;
    for (int i = threadIdx.x; i < CC * 128; i += 256) {
        int c = i >> 7, j = i & 127;
        xs[c][j] = x[c * NN + n0 + j];
    }
    __syncthreads();
    int tx = threadIdx.x & 15, ty = threadIdx.x >> 4;
    int ci0 = ty * 4, cj0 = tx * 4;
    float acc[4][4];
    #pragma unroll
    for (int i = 0; i < 4; i++)
        #pragma unroll
        for (int j = 0; j < 4; j++) acc[i][j] = 0.f;
    for (int j = 0; j < 128; j += 4) {
        float4 a[4], bvv[4];
        #pragma unroll
        for (int i = 0; i < 4; i++) a[i] = *(const float4*)&xs[ci0 + i][j];
        #pragma unroll
        for (int i = 0; i < 4; i++) bvv[i] = *(const float4*)&xs[cj0 + i][j];
        #pragma unroll
        for (int i = 0; i < 4; i++)
            #pragma unroll
            for (int jj = 0; jj < 4; jj++)
                acc[i][jj] += a[i].x * bvv[jj].x + a[i].y * bvv[jj].y
                            + a[i].z * bvv[jj].z + a[i].w * bvv[jj].w;
    }
    float* outp = g_gpart + (chunk * NIMG + img) * CC * CC;
    #pragma unroll
    for (int i = 0; i < 4; i++)
        *(float4*)&outp[(ci0 + i) * CC + cj0] =
            make_float4(acc[i][0], acc[i][1], acc[i][2], acc[i][3]);
}

// ---------------- Stage A2: reduce + softmax + effective-weight compose --------
__global__ void k_prep(const float* __restrict__ Wq, const float* __restrict__ Wk,
                       const float* __restrict__ Wv,
                       const float* __restrict__ gcnn, const float* __restrict__ gvit) {
    int img = blockIdx.x;
    int tid = threadIdx.x;
    __shared__ __align__(16) float As[CC * CC];
    __shared__ __align__(16) float Wvs[CC * 68];
    __shared__ float Wqs[CC * C8V];

    for (int p = tid; p < CC * CC; p += 256) {
        float s = 0.f;
        #pragma unroll
        for (int ch = 0; ch < NCHUNK; ch++)
            s += g_gpart[(ch * NIMG + img) * CC * CC + p];
        As[p] = s;
    }
    __syncthreads();

    {
        int r = tid >> 2, l4 = tid & 3;
        float m = -1e30f;
        for (int d = l4; d < CC; d += 4) m = fmaxf(m, -As[r * CC + d]);
        m = fmaxf(m, __shfl_xor_sync(0xffffffffu, m, 1));
        m = fmaxf(m, __shfl_xor_sync(0xffffffffu, m, 2));
        float s = 0.f;
        for (int d = l4; d < CC; d += 4) s += __expf(-As[r * CC + d] - m);
        s += __shfl_xor_sync(0xffffffffu, s, 1);
        s += __shfl_xor_sync(0xffffffffu, s, 2);
        float inv = 1.f / s;
        for (int d = l4; d < CC; d += 4)
            As[r * CC + d] = __expf(-As[r * CC + d] - m) * inv;
    }

    const float* Wsm = (img < BB) ? Wq : Wk;
    for (int i = tid; i < C8V * CC; i += 256)
        Wqs[(i & 63) * C8V + (i >> 6)] = Wsm[i];
    if (img >= BB) {
        for (int i = tid; i < CC * CC; i += 256)
            Wvs[(i & 63) * 68 + (i >> 6)] = Wv[i];
    }
    __syncthreads();

    if (img < BB) {
        float g = gcnn[0];
        for (int p = tid; p < CC * C8V; p += 256) {
            int d = p >> 3, o = p & 7;
            float s = 0.f;
            #pragma unroll 4
            for (int c = 0; c < CC; c++) s += Wqs[c * C8V + o] * As[c * CC + d];
            g_WqT[img * CC * C8V + d * C8V + o] = (Wqs[d * C8V + o] + g * s) * RLN2;
        }
    } else {
        int b = img - BB;
        float g = gvit[0];
        for (int p = tid; p < CC * C8V; p += 256) {
            int d = p >> 3, o = p & 7;
            float s = 0.f;
            #pragma unroll 4
            for (int c = 0; c < CC; c++) s += Wqs[c * C8V + o] * As[c * CC + d];
            g_WkT[b * CC * C8V + d * C8V + o] = Wqs[d * C8V + o] + g * s;
        }
        int tx = tid & 15, ty = tid >> 4;
        int o0 = tx * 4, d0 = ty * 4;
        float acc[4][4];
        #pragma unroll
        for (int i = 0; i < 4; i++)
            #pragma unroll
            for (int j = 0; j < 4; j++) acc[i][j] = 0.f;
        for (int c = 0; c < CC; c++) {
            float4 a = *(const float4*)&As[c * CC + d0];
            float4 wv = *(const float4*)&Wvs[c * 68 + o0];
            float ar[4] = {a.x, a.y, a.z, a.w};
            float wr[4] = {wv.x, wv.y, wv.z, wv.w};
            #pragma unroll
            for (int i = 0; i < 4; i++)
                #pragma unroll
                for (int j = 0; j < 4; j++) acc[i][j] += ar[i] * wr[j];
        }
        #pragma unroll
        for (int i = 0; i < 4; i++) {
            float4 wd = *(const float4*)&Wvs[(d0 + i) * 68 + o0];
            float4 o = make_float4(wd.x + g * acc[i][0], wd.y + g * acc[i][1],
                                   wd.z + g * acc[i][2], wd.w + g * acc[i][3]);
            *(float4*)&g_WvTe[b * CC * CC + (d0 + i) * CC + o0] = o;
        }
    }
}

// ---------------- Stage B: fused q/k/v projections ------------------------------
__global__ void __launch_bounds__(192) k_qkv(const float* __restrict__ cnn,
                                             const float* __restrict__ vit,
                                             const float* __restrict__ bq,
                                             const float* __restrict__ bk,
                                             const float* __restrict__ bv) {
    int n0 = blockIdx.x * 32, b = blockIdx.y;
    int tid = threadIdx.x, ww = tid >> 5, lane = tid & 31;
    int n = n0 + lane;

    __shared__ __align__(16) float Wvs[CC * CC];
    __shared__ __align__(16) float Wqs[CC * C8V];
    __shared__ __align__(16) float Wks[CC * C8V];

    const float* wsrc = g_WvTe + b * CC * CC;
    for (int i = tid; i < CC * CC / 4; i += 192)
        *(float4*)&Wvs[i * 4] = *(const float4*)&wsrc[i * 4];
    if (tid < 128) {
        *(float4*)&Wqs[tid * 4] = *(const float4*)&g_WqT[b * CC * C8V + tid * 4];
        *(float4*)&Wks[tid * 4] = *(const float4*)&g_WkT[b * CC * C8V + tid * 4];
    }
    __syncthreads();

    if (ww < 4) {
        int og = ww * 16;
        const float* src = vit + (size_t)b * CC * NN;
        float acc[16];
        #pragma unroll
        for (int i = 0; i < 16; i++) acc[i] = bv[og + i];
        #pragma unroll 4
        for (int c = 0; c < CC; c++) {
            float xv = src[c * NN + n];
            #pragma unroll
            for (int m = 0; m < 4; m++) {
                float4 w = *(const float4*)&Wvs[c * CC + og + m * 4];
                acc[m * 4 + 0] += w.x * xv; acc[m * 4 + 1] += w.y * xv;
                acc[m * 4 + 2] += w.z * xv; acc[m * 4 + 3] += w.w * xv;
            }
        }
        __half* dst = g_v + ((size_t)(b * NN + n)) * CC + og;
        #pragma unroll
        for (int m = 0; m < 4; m++) {
            ushort4 u;
            u.x = __half_as_ushort(__float2half(acc[m * 4 + 0]));
            u.y = __half_as_ushort(__float2half(acc[m * 4 + 1]));
            u.z = __half_as_ushort(__float2half(acc[m * 4 + 2]));
            u.w = __half_as_ushort(__float2half(acc[m * 4 + 3]));
            *(ushort4*)(dst + m * 4) = u;
        }
    } else {
        bool isQ = (ww == 4);
        const float* src = (isQ ? cnn : vit) + (size_t)b * CC * NN;
        const float* Ws = isQ ? Wqs : Wks;
        const float* bias = isQ ? bq : bk;
        float bscale = isQ ? RLN2 : 1.0f;
        __nv_bfloat16* dst = isQ ? g_qb : g_kb;
        float acc[8];
        #pragma unroll
        for (int o = 0; o < 8; o++) acc[o] = bias[o] * bscale;
        #pragma unroll 8
        for (int c = 0; c < CC; c++) {
            float xv = src[c * NN + n];
            float4 w0 = *(const float4*)&Ws[c * C8V];
            float4 w1 = *(const float4*)&Ws[c * C8V + 4];
            acc[0] += w0.x * xv; acc[1] += w0.y * xv; acc[2] += w0.z * xv; acc[3] += w0.w * xv;
            acc[4] += w1.x * xv; acc[5] += w1.y * xv; acc[6] += w1.z * xv; acc[7] += w1.w * xv;
        }
        ushort4 u0, u1;
        u0.x = __bfloat16_as_ushort(__float2bfloat16(acc[0]));
        u0.y = __bfloat16_as_ushort(__float2bfloat16(acc[1]));
        u0.z = __bfloat16_as_ushort(__float2bfloat16(acc[2]));
        u0.w = __bfloat16_as_ushort(__float2bfloat16(acc[3]));
        u1.x = __bfloat16_as_ushort(__float2bfloat16(acc[4]));
        u1.y = __bfloat16_as_ushort(__float2bfloat16(acc[5]));
        u1.z = __bfloat16_as_ushort(__float2bfloat16(acc[6]));
        u1.w = __bfloat16_as_ushort(__float2bfloat16(acc[7]));
        *(ushort4*)(dst + ((size_t)(b * NN + n)) * 8)     = u0;
        *(ushort4*)(dst + ((size_t)(b * NN + n)) * 8 + 4) = u1;
    }
}

// ---------------- Stage C: mma attention, 64 q rows per warp -------------------
// grid (8, 4, 8), 256 threads (8 warps x 64 q rows = 512 q rows/CTA).
// f16x2 packed accumulators; ones-column row-sums; packed partial store.
__global__ void __launch_bounds__(256, 2) k_attn() {
    int qt = blockIdx.x, b = blockIdx.y, sp = blockIdx.z;
    int tid = threadIdx.x;
    int w = tid >> 5, lane = tid & 31;
    int g = lane >> 2, tp = lane & 3;
    int kbase = sp * (NN / KSPL);

    __shared__ __align__(16) __nv_bfloat16 Ks[2][128][8];
    __shared__ __align__(16) __half        Vs[2][128][72];

    // ones columns (col 64 = 1.0, cols 65..71 = 0); never touched by cp.async
    for (int i = tid; i < 2 * 128; i += 256) {
        uint4 z; z.x = 0x00003C00u; z.y = 0; z.z = 0; z.w = 0;
        *(uint4*)&Vs[i >> 7][i & 127][64] = z;
    }
    __syncthreads();

    uint32_t vbO0, vbO1;
    asm volatile("ldmatrix.sync.aligned.m8n8.x2.trans.shared.b16 {%0,%1}, [%2];"
                 : "=r"(vbO0), "=r"(vbO1) : "r"(smem_u32(&Vs[0][lane & 15][64])));

    int qrow = qt * 512 + w * 64;
    uint32_t qa[4][2];
    #pragma unroll
    for (int i = 0; i < 4; i++) {
        qa[i][0] = *(const uint32_t*)(g_qb + ((size_t)(b * NN + qrow + i * 16 + g)) * 8 + 2 * tp);
        qa[i][1] = *(const uint32_t*)(g_qb + ((size_t)(b * NN + qrow + i * 16 + g + 8)) * 8 + 2 * tp);
    }

    uint32_t d2[4][9][2];      // packed f16x2 accumulators
    #pragma unroll
    for (int i = 0; i < 4; i++)
        #pragma unroll
        for (int j = 0; j < 9; j++) { d2[i][j][0] = 0u; d2[i][j][1] = 0u; }

    {
        if (tid < 128) CP16(smem_u32(&Ks[0][tid][0]), g_kb + ((size_t)(b * NN + kbase + tid)) * 8);
        #pragma unroll
        for (int i2 = 0; i2 < 4; i2++) {
            int idx = tid + i2 * 256, key = idx >> 3, c8 = (idx & 7) * 8;
            CP16(smem_u32(&Vs[0][key][c8]), g_v + ((size_t)(b * NN + kbase + key)) * CC + c8);
        }
        CP_COMMIT();
    }

    for (int t = 0; t < NTILE; t++) {
        if (t + 1 < NTILE) {
            int nb = (t + 1) & 1, k0 = kbase + (t + 1) * 128;
            if (tid < 128) CP16(smem_u32(&Ks[nb][tid][0]), g_kb + ((size_t)(b * NN + k0 + tid)) * 8);
            #pragma unroll
            for (int i2 = 0; i2 < 4; i2++) {
                int idx = tid + i2 * 256, key = idx >> 3, c8 = (idx & 7) * 8;
                CP16(smem_u32(&Vs[nb][key][c8]), g_v + ((size_t)(b * NN + k0 + key)) * CC + c8);
            }
            CP_COMMIT();
            asm volatile("cp.async.wait_group 1;" ::: "memory");
        } else {
            asm volatile("cp.async.wait_group 0;" ::: "memory");
        }
        __syncthreads();
        int bs = t & 1;

        uint32_t aK = smem_u32(&Ks[bs][lane & 15][0]);
        uint32_t aV = smem_u32(&Vs[bs][lane & 15][(lane >> 4) * 8]);
        #pragma unroll 2
        for (int kc = 0; kc < 8; kc++) {
            uint32_t kb0, kb1;
            asm volatile("ldmatrix.sync.aligned.m8n8.x2.shared.b16 {%0,%1}, [%2];"
                         : "=r"(kb0), "=r"(kb1) : "r"(aK));
            uint32_t vb[8][2];
            #pragma unroll
            for (int m = 0; m < 4; m++) {
                asm volatile("ldmatrix.sync.aligned.m8n8.x4.trans.shared.b16 {%0,%1,%2,%3}, [%4];"
                             : "=r"(vb[2 * m][0]), "=r"(vb[2 * m][1]),
                               "=r"(vb[2 * m + 1][0]), "=r"(vb[2 * m + 1][1])
                             : "r"(aV + m * 32));
            }
            aK += 16 * 16;
            aV += 16 * 144;
            #pragma unroll
            for (int i = 0; i < 4; i++) {
                float s0[4] = {0.f, 0.f, 0.f, 0.f}, s1[4] = {0.f, 0.f, 0.f, 0.f};
                MMA_BF16_K8(s0, qa[i][0], qa[i][1], kb0);
                MMA_BF16_K8(s1, qa[i][0], qa[i][1], kb1);
                uint32_t pa0, pa1, pa2, pa3;
                asm("cvt.rn.f16x2.f32 %0, %1, %2;" : "=r"(pa0) : "f"(s0[1]), "f"(s0[0]));
                asm("cvt.rn.f16x2.f32 %0, %1, %2;" : "=r"(pa1) : "f"(s0[3]), "f"(s0[2]));
                asm("cvt.rn.f16x2.f32 %0, %1, %2;" : "=r"(pa2) : "f"(s1[1]), "f"(s1[0]));
                asm("cvt.rn.f16x2.f32 %0, %1, %2;" : "=r"(pa3) : "f"(s1[3]), "f"(s1[2]));
                asm("ex2.approx.f16x2 %0, %0;" : "+r"(pa0));
                asm("ex2.approx.f16x2 %0, %0;" : "+r"(pa1));
                asm("ex2.approx.f16x2 %0, %0;" : "+r"(pa2));
                asm("ex2.approx.f16x2 %0, %0;" : "+r"(pa3));
                #pragma unroll
                for (int j = 0; j < 8; j++)
                    MMA_F16_H(d2[i][j], pa0, pa1, pa2, pa3, vb[j][0], vb[j][1]);
                MMA_F16_H(d2[i][8], pa0, pa1, pa2, pa3, vbO0, vbO1);
            }
        }
        __syncthreads();
    }

    // store packed partials; l is col 64 (low half of ones-block frags)
    int bs2 = b * KSPL + sp;
    uint32_t* pD = g_pDh + (size_t)bs2 * (CC / 2) * NN;
    #pragma unroll
    for (int i = 0; i < 4; i++) {
        int q0 = qrow + i * 16 + g, q1 = q0 + 8;
        if (tp == 0) {
            float2 l0 = __half22float2(*reinterpret_cast<__half2*>(&d2[i][8][0]));
            float2 l1 = __half22float2(*reinterpret_cast<__half2*>(&d2[i][8][1]));
            g_pl[(size_t)bs2 * NN + q0] = l0.x;
            g_pl[(size_t)bs2 * NN + q1] = l1.x;
        }
        #pragma unroll
        for (int j = 0; j < 8; j++) {
            int cp = j * 4 + tp;                       // channel pair (2cp, 2cp+1)
            pD[(size_t)cp * NN + q0] = d2[i][j][0];
            pD[(size_t)cp * NN + q1] = d2[i][j][1];
        }
    }
}

// ---------------- Stage D: combine splits + epilogue ----------------------------
__global__ void __launch_bounds__(256) k_comb(const float* __restrict__ gamma,
                                              const float* __restrict__ cnn,
                                              float* __restrict__ out) {
    int b = blockIdx.y;
    int q = blockIdx.x * 128 + (threadIdx.x & 127);
    int cp0 = (threadIdx.x >> 7) * 16;                 // 16 channel-pairs per thread
    float l = 0.f;
    #pragma unroll
    for (int s = 0; s < KSPL; s++) l += g_pl[(size_t)(b * KSPL + s) * NN + q];
    float inv = gamma[0] / l;
    const float* cb = cnn + (size_t)b * CC * NN + q;
    float* ob = out + (size_t)b * CC * NN + q;
    #pragma unroll 4
    for (int i = 0; i < 16; i++) {
        int cp = cp0 + i;
        float a0 = 0.f, a1 = 0.f;
        #pragma unroll
        for (int s = 0; s < KSPL; s++) {
            uint32_t v = g_pDh[((size_t)(b * KSPL + s) * (CC / 2) + cp) * NN + q];
            float2 f = __half22float2(*reinterpret_cast<__half2*>(&v));
            a0 += f.x; a1 += f.y;
        }
        ob[(size_t)(2 * cp) * NN]     = a0 * inv + cb[(size_t)(2 * cp) * NN];
        ob[(size_t)(2 * cp + 1) * NN] = a1 * inv + cb[(size_t)(2 * cp + 1) * NN];
    }
}

// ---------------- launch ---------------------------------------------------------
extern "C" void kernel_launch(void* const* d_in, const int* in_sizes, int n_in,
                              void* d_out, int out_size) {
    const float* cnn   = (const float*)d_in[0];
    const float* vit   = (const float*)d_in[1];
    const float* Wq    = (const float*)d_in[2];
    const float* bq    = (const float*)d_in[3];
    const float* Wk    = (const float*)d_in[4];
    const float* bk    = (const float*)d_in[5];
    const float* Wv    = (const float*)d_in[6];
    const float* bv    = (const float*)d_in[7];
    const float* gamma = (const float*)d_in[8];
    const float* gcnn  = (const float*)d_in[9];
    const float* gvit  = (const float*)d_in[10];
    float* out = (float*)d_out;

    k_gram <<<dim3(NCHUNK, NIMG), 256>>>(cnn, vit);
    k_prep <<<NIMG, 256>>>(Wq, Wk, Wv, gcnn, gvit);
    k_qkv  <<<dim3(NN / 32, BB), 192>>>(cnn, vit, bq, bk, bv);
    k_attn <<<dim3(NN / 512, BB, KSPL), 256>>>();
    k_comb <<<dim3(NN / 128, BB), 256>>>(gamma, cnn, out);
}

// round 14
// speedup vs baseline: 1.2532x; 1.2532x over previous
#include <cuda_runtime.h>
#include <cuda_bf16.h>
#include <cuda_fp16.h>
#include <cstdint>

// Problem constants
#define BB 4
#define CC 64
#define NN 4096
#define C8V 8
#define NIMG 8
#define NCHUNK 32
#define KSPL 4
#define NTILE (NN / KSPL / 128)
#define RLN2 1.4426950408889634f

// ---------------- scratch ----------------------------------------------------
__device__ float g_gpart[NCHUNK * NIMG * CC * CC];
__device__ float g_WqT[BB * CC * C8V];             // [b][c][o], prescaled by 1/ln2
__device__ float g_WkT[BB * CC * C8V];             // [b][c][o]
__device__ float g_WvTe[BB * CC * CC];             // [b][c][o]
__device__ __nv_bfloat16 g_qb[BB * NN * C8V];      // [b][n][8] (prescaled 1/ln2)
__device__ __nv_bfloat16 g_kb[BB * NN * C8V];      // [b][n][8]
__device__ __half        g_v [BB * NN * CC];       // [b][n][c]
__device__ uint32_t g_pDh[BB * KSPL * (CC / 2) * NN];  // packed f16x2 partials [b][s][cp][q]
__device__ float g_pl[BB * KSPL * NN];             // partial row-sums [b][s][q]

__device__ __forceinline__ uint32_t smem_u32(const void* p) {
    uint32_t a;
    asm("{ .reg .u64 t; cvta.to.shared.u64 t, %1; cvt.u32.u64 %0, t; }" : "=r"(a) : "l"(p));
    return a;
}

#define MMA_BF16_K8(d, a0, a1, b0)                                                 \
    asm volatile("mma.sync.aligned.m16n8k8.row.col.f32.bf16.bf16.f32 "             \
        "{%0,%1,%2,%3}, {%4,%5}, {%6}, {%0,%1,%2,%3};"                             \
        : "+f"((d)[0]), "+f"((d)[1]), "+f"((d)[2]), "+f"((d)[3])                   \
        : "r"(a0), "r"(a1), "r"(b0))

#define MMA_F16(d, a0, a1, a2, a3, b0, b1)                                         \
    asm volatile("mma.sync.aligned.m16n8k16.row.col.f32.f16.f16.f32 "              \
        "{%0,%1,%2,%3}, {%4,%5,%6,%7}, {%8,%9}, {%0,%1,%2,%3};"                    \
        : "+f"((d)[0]), "+f"((d)[1]), "+f"((d)[2]), "+f"((d)[3])                   \
        : "r"(a0), "r"(a1), "r"(a2), "r"(a3), "r"(b0), "r"(b1))

#define MMA_BF16_K16(d, a0, a1, a2, a3, b0, b1)                                    \
    asm volatile("mma.sync.aligned.m16n8k16.row.col.f32.bf16.bf16.f32 "            \
        "{%0,%1,%2,%3}, {%4,%5,%6,%7}, {%8,%9}, {%0,%1,%2,%3};"                    \
        : "+f"((d)[0]), "+f"((d)[1]), "+f"((d)[2]), "+f"((d)[3])                   \
        : "r"(a0), "r"(a1), "r"(a2), "r"(a3), "r"(b0), "r"(b1))

#define LDSM_X4(r0, r1, r2, r3, addr)                                              \
    asm volatile("ldmatrix.sync.aligned.m8n8.x4.shared.b16 {%0,%1,%2,%3}, [%4];"   \
                 : "=r"(r0), "=r"(r1), "=r"(r2), "=r"(r3) : "r"(addr))

#define CP16(dst, src) asm volatile("cp.async.cg.shared.global [%0], [%1], 16;" :: "r"(dst), "l"(src) : "memory")
#define CP_COMMIT()    asm volatile("cp.async.commit_group;" ::: "memory")

// ---------------- Stage A1: gram partials via tensor cores (split-bf16) --------
// grid (32, 8), 256 threads (8 warps). Each CTA: one img, 128-col chunk.
// G_partial = Ah.Bh^T + Ah.Bl^T + Al.Bh^T  (fp32 accum), error ~2^-16.
#define GROWS 144   // smem row stride (elems): 288B, 16B-multiple
__global__ void __launch_bounds__(256) k_gram(const float* __restrict__ cnn,
                                              const float* __restrict__ vit) {
    int chunk = blockIdx.x, img = blockIdx.y;
    const float* x = (img < BB) ? (cnn + img * CC * NN) : (vit + (img - BB) * CC * NN);
    __shared__ __align__(16) __nv_bfloat16 xh[CC][GROWS];
    __shared__ __align__(16) __nv_bfloat16 xl[CC][GROWS];
    int tid = threadIdx.x;
    int n0 = chunk * 128;

    // convert fp32 -> (hi, lo) bf16 pairs
    for (int i = tid; i < CC * 64; i += 256) {
        int c = i >> 6, j2 = (i & 63) * 2;
        float2 v = *(const float2*)(x + c * NN + n0 + j2);
        __nv_bfloat16 h0 = __float2bfloat16(v.x);
        __nv_bfloat16 h1 = __float2bfloat16(v.y);
        __nv_bfloat16 l0 = __float2bfloat16(v.x - __bfloat162float(h0));
        __nv_bfloat16 l1 = __float2bfloat16(v.y - __bfloat162float(h1));
        uint32_t hp = ((uint32_t)__bfloat16_as_ushort(h1) << 16) | __bfloat16_as_ushort(h0);
        uint32_t lp = ((uint32_t)__bfloat16_as_ushort(l1) << 16) | __bfloat16_as_ushort(l0);
        *(uint32_t*)&xh[c][j2] = hp;
        *(uint32_t*)&xl[c][j2] = lp;
    }
    __syncthreads();

    int w = tid >> 5, lane = tid & 31;
    int g = lane >> 2, tp = lane & 3;
    int mi = w & 3, nh = w >> 2;
    int m0 = mi * 16, cj0 = nh * 32;

    // base ldmatrix addresses
    uint32_t aAh = smem_u32(&xh[m0 + (lane & 15)][(lane >> 4) * 8]);
    uint32_t aAl = smem_u32(&xl[m0 + (lane & 15)][(lane >> 4) * 8]);
    uint32_t aBh = smem_u32(&xh[cj0 + ((lane >> 4) & 1) * 8 + (lane & 7)][((lane >> 3) & 1) * 8]);
    uint32_t aBl = smem_u32(&xl[cj0 + ((lane >> 4) & 1) * 8 + (lane & 7)][((lane >> 3) & 1) * 8]);
    const uint32_t BOFF2 = 16u * (GROWS * 2);   // +16 rows for blocks 2,3

    float d[4][4];
    #pragma unroll
    for (int b2 = 0; b2 < 4; b2++)
        #pragma unroll
        for (int r = 0; r < 4; r++) d[b2][r] = 0.f;

    #pragma unroll
    for (int ks = 0; ks < 8; ks++) {
        uint32_t ah0, ah1, ah2, ah3, al0, al1, al2, al3;
        LDSM_X4(ah0, ah1, ah2, ah3, aAh);
        LDSM_X4(al0, al1, al2, al3, aAl);
        uint32_t bh[8], bl[8];
        LDSM_X4(bh[0], bh[1], bh[2], bh[3], aBh);
        LDSM_X4(bh[4], bh[5], bh[6], bh[7], aBh + BOFF2);
        LDSM_X4(bl[0], bl[1], bl[2], bl[3], aBl);
        LDSM_X4(bl[4], bl[5], bl[6], bl[7], aBl + BOFF2);
        aAh += 32; aAl += 32; aBh += 32; aBl += 32;
        #pragma unroll
        for (int b2 = 0; b2 < 4; b2++) {
            MMA_BF16_K16(d[b2], ah0, ah1, ah2, ah3, bh[2 * b2], bh[2 * b2 + 1]);
            MMA_BF16_K16(d[b2], ah0, ah1, ah2, ah3, bl[2 * b2], bl[2 * b2 + 1]);
            MMA_BF16_K16(d[b2], al0, al1, al2, al3, bh[2 * b2], bh[2 * b2 + 1]);
        }
    }

    float* outp = g_gpart + (chunk * NIMG + img) * CC * CC;
    #pragma unroll
    for (int b2 = 0; b2 < 4; b2++) {
        int col = cj0 + b2 * 8 + 2 * tp;
        *(float2*)&outp[(m0 + g) * CC + col]     = make_float2(d[b2][0], d[b2][1]);
        *(float2*)&outp[(m0 + g + 8) * CC + col] = make_float2(d[b2][2], d[b2][3]);
    }
}

// ---------------- Stage A2: reduce + softmax + effective-weight compose --------
__global__ void k_prep(const float* __restrict__ Wq, const float* __restrict__ Wk,
                       const float* __restrict__ Wv,
                       const float* __restrict__ gcnn, const float* __restrict__ gvit) {
    int img = blockIdx.x;
    int tid = threadIdx.x;
    __shared__ __align__(16) float As[CC * CC];
    __shared__ __align__(16) float Wvs[CC * 68];
    __shared__ float Wqs[CC * C8V];

    for (int p = tid; p < CC * CC; p += 256) {
        float s = 0.f;
        #pragma unroll
        for (int ch = 0; ch < NCHUNK; ch++)
            s += g_gpart[(ch * NIMG + img) * CC * CC + p];
        As[p] = s;
    }
    __syncthreads();

    {
        int r = tid >> 2, l4 = tid & 3;
        float m = -1e30f;
        for (int d = l4; d < CC; d += 4) m = fmaxf(m, -As[r * CC + d]);
        m = fmaxf(m, __shfl_xor_sync(0xffffffffu, m, 1));
        m = fmaxf(m, __shfl_xor_sync(0xffffffffu, m, 2));
        float s = 0.f;
        for (int d = l4; d < CC; d += 4) s += __expf(-As[r * CC + d] - m);
        s += __shfl_xor_sync(0xffffffffu, s, 1);
        s += __shfl_xor_sync(0xffffffffu, s, 2);
        float inv = 1.f / s;
        for (int d = l4; d < CC; d += 4)
            As[r * CC + d] = __expf(-As[r * CC + d] - m) * inv;
    }

    const float* Wsm = (img < BB) ? Wq : Wk;
    for (int i = tid; i < C8V * CC; i += 256)
        Wqs[(i & 63) * C8V + (i >> 6)] = Wsm[i];
    if (img >= BB) {
        for (int i = tid; i < CC * CC; i += 256)
            Wvs[(i & 63) * 68 + (i >> 6)] = Wv[i];
    }
    __syncthreads();

    if (img < BB) {
        float g = gcnn[0];
        for (int p = tid; p < CC * C8V; p += 256) {
            int d = p >> 3, o = p & 7;
            float s = 0.f;
            #pragma unroll 4
            for (int c = 0; c < CC; c++) s += Wqs[c * C8V + o] * As[c * CC + d];
            g_WqT[img * CC * C8V + d * C8V + o] = (Wqs[d * C8V + o] + g * s) * RLN2;
        }
    } else {
        int b = img - BB;
        float g = gvit[0];
        for (int p = tid; p < CC * C8V; p += 256) {
            int d = p >> 3, o = p & 7;
            float s = 0.f;
            #pragma unroll 4
            for (int c = 0; c < CC; c++) s += Wqs[c * C8V + o] * As[c * CC + d];
            g_WkT[b * CC * C8V + d * C8V + o] = Wqs[d * C8V + o] + g * s;
        }
        int tx = tid & 15, ty = tid >> 4;
        int o0 = tx * 4, d0 = ty * 4;
        float acc[4][4];
        #pragma unroll
        for (int i = 0; i < 4; i++)
            #pragma unroll
            for (int j = 0; j < 4; j++) acc[i][j] = 0.f;
        for (int c = 0; c < CC; c++) {
            float4 a = *(const float4*)&As[c * CC + d0];
            float4 wv = *(const float4*)&Wvs[c * 68 + o0];
            float ar[4] = {a.x, a.y, a.z, a.w};
            float wr[4] = {wv.x, wv.y, wv.z, wv.w};
            #pragma unroll
            for (int i = 0; i < 4; i++)
                #pragma unroll
                for (int j = 0; j < 4; j++) acc[i][j] += ar[i] * wr[j];
        }
        #pragma unroll
        for (int i = 0; i < 4; i++) {
            float4 wd = *(const float4*)&Wvs[(d0 + i) * 68 + o0];
            float4 o = make_float4(wd.x + g * acc[i][0], wd.y + g * acc[i][1],
                                   wd.z + g * acc[i][2], wd.w + g * acc[i][3]);
            *(float4*)&g_WvTe[b * CC * CC + (d0 + i) * CC + o0] = o;
        }
    }
}

// ---------------- Stage B: fused q/k/v projections ------------------------------
__global__ void __launch_bounds__(192) k_qkv(const float* __restrict__ cnn,
                                             const float* __restrict__ vit,
                                             const float* __restrict__ bq,
                                             const float* __restrict__ bk,
                                             const float* __restrict__ bv) {
    int n0 = blockIdx.x * 32, b = blockIdx.y;
    int tid = threadIdx.x, ww = tid >> 5, lane = tid & 31;
    int n = n0 + lane;

    __shared__ __align__(16) float Wvs[CC * CC];
    __shared__ __align__(16) float Wqs[CC * C8V];
    __shared__ __align__(16) float Wks[CC * C8V];

    const float* wsrc = g_WvTe + b * CC * CC;
    for (int i = tid; i < CC * CC / 4; i += 192)
        *(float4*)&Wvs[i * 4] = *(const float4*)&wsrc[i * 4];
    if (tid < 128) {
        *(float4*)&Wqs[tid * 4] = *(const float4*)&g_WqT[b * CC * C8V + tid * 4];
        *(float4*)&Wks[tid * 4] = *(const float4*)&g_WkT[b * CC * C8V + tid * 4];
    }
    __syncthreads();

    if (ww < 4) {
        int og = ww * 16;
        const float* src = vit + (size_t)b * CC * NN;
        float acc[16];
        #pragma unroll
        for (int i = 0; i < 16; i++) acc[i] = bv[og + i];
        #pragma unroll 4
        for (int c = 0; c < CC; c++) {
            float xv = src[c * NN + n];
            #pragma unroll
            for (int m = 0; m < 4; m++) {
                float4 w = *(const float4*)&Wvs[c * CC + og + m * 4];
                acc[m * 4 + 0] += w.x * xv; acc[m * 4 + 1] += w.y * xv;
                acc[m * 4 + 2] += w.z * xv; acc[m * 4 + 3] += w.w * xv;
            }
        }
        __half* dst = g_v + ((size_t)(b * NN + n)) * CC + og;
        #pragma unroll
        for (int m = 0; m < 4; m++) {
            ushort4 u;
            u.x = __half_as_ushort(__float2half(acc[m * 4 + 0]));
            u.y = __half_as_ushort(__float2half(acc[m * 4 + 1]));
            u.z = __half_as_ushort(__float2half(acc[m * 4 + 2]));
            u.w = __half_as_ushort(__float2half(acc[m * 4 + 3]));
            *(ushort4*)(dst + m * 4) = u;
        }
    } else {
        bool isQ = (ww == 4);
        const float* src = (isQ ? cnn : vit) + (size_t)b * CC * NN;
        const float* Ws = isQ ? Wqs : Wks;
        const float* bias = isQ ? bq : bk;
        float bscale = isQ ? RLN2 : 1.0f;
        __nv_bfloat16* dst = isQ ? g_qb : g_kb;
        float acc[8];
        #pragma unroll
        for (int o = 0; o < 8; o++) acc[o] = bias[o] * bscale;
        #pragma unroll 8
        for (int c = 0; c < CC; c++) {
            float xv = src[c * NN + n];
            float4 w0 = *(const float4*)&Ws[c * C8V];
            float4 w1 = *(const float4*)&Ws[c * C8V + 4];
            acc[0] += w0.x * xv; acc[1] += w0.y * xv; acc[2] += w0.z * xv; acc[3] += w0.w * xv;
            acc[4] += w1.x * xv; acc[5] += w1.y * xv; acc[6] += w1.z * xv; acc[7] += w1.w * xv;
        }
        ushort4 u0, u1;
        u0.x = __bfloat16_as_ushort(__float2bfloat16(acc[0]));
        u0.y = __bfloat16_as_ushort(__float2bfloat16(acc[1]));
        u0.z = __bfloat16_as_ushort(__float2bfloat16(acc[2]));
        u0.w = __bfloat16_as_ushort(__float2bfloat16(acc[3]));
        u1.x = __bfloat16_as_ushort(__float2bfloat16(acc[4]));
        u1.y = __bfloat16_as_ushort(__float2bfloat16(acc[5]));
        u1.z = __bfloat16_as_ushort(__float2bfloat16(acc[6]));
        u1.w = __bfloat16_as_ushort(__float2bfloat16(acc[7]));
        *(ushort4*)(dst + ((size_t)(b * NN + n)) * 8)     = u0;
        *(ushort4*)(dst + ((size_t)(b * NN + n)) * 8 + 4) = u1;
    }
}

// ---------------- Stage C: mma attention (R12 best config, unchanged) ----------
__global__ void __launch_bounds__(256, 2) k_attn() {
    int qt = blockIdx.x, b = blockIdx.y, sp = blockIdx.z;
    int tid = threadIdx.x;
    int w = tid >> 5, lane = tid & 31;
    int g = lane >> 2, tp = lane & 3;
    int kbase = sp * (NN / KSPL);

    __shared__ __align__(16) __nv_bfloat16 Ks[2][128][8];
    __shared__ __align__(16) __half        Vs[2][128][72];

    for (int i = tid; i < 2 * 128; i += 256) {
        uint4 z; z.x = 0x00003C00u; z.y = 0; z.z = 0; z.w = 0;
        *(uint4*)&Vs[i >> 7][i & 127][64] = z;
    }
    __syncthreads();

    uint32_t vbO0, vbO1;
    asm volatile("ldmatrix.sync.aligned.m8n8.x2.trans.shared.b16 {%0,%1}, [%2];"
                 : "=r"(vbO0), "=r"(vbO1) : "r"(smem_u32(&Vs[0][lane & 15][64])));

    int qrow = qt * 256 + w * 32;
    uint32_t qa[2][2];
    #pragma unroll
    for (int i = 0; i < 2; i++) {
        qa[i][0] = *(const uint32_t*)(g_qb + ((size_t)(b * NN + qrow + i * 16 + g)) * 8 + 2 * tp);
        qa[i][1] = *(const uint32_t*)(g_qb + ((size_t)(b * NN + qrow + i * 16 + g + 8)) * 8 + 2 * tp);
    }

    float d2[2][9][4];
    #pragma unroll
    for (int i = 0; i < 2; i++)
        #pragma unroll
        for (int j = 0; j < 9; j++)
            #pragma unroll
            for (int r = 0; r < 4; r++) d2[i][j][r] = 0.f;

    {
        if (tid < 128) CP16(smem_u32(&Ks[0][tid][0]), g_kb + ((size_t)(b * NN + kbase + tid)) * 8);
        #pragma unroll
        for (int i2 = 0; i2 < 4; i2++) {
            int idx = tid + i2 * 256, key = idx >> 3, c8 = (idx & 7) * 8;
            CP16(smem_u32(&Vs[0][key][c8]), g_v + ((size_t)(b * NN + kbase + key)) * CC + c8);
        }
        CP_COMMIT();
    }

    for (int t = 0; t < NTILE; t++) {
        if (t + 1 < NTILE) {
            int nb = (t + 1) & 1, k0 = kbase + (t + 1) * 128;
            if (tid < 128) CP16(smem_u32(&Ks[nb][tid][0]), g_kb + ((size_t)(b * NN + k0 + tid)) * 8);
            #pragma unroll
            for (int i2 = 0; i2 < 4; i2++) {
                int idx = tid + i2 * 256, key = idx >> 3, c8 = (idx & 7) * 8;
                CP16(smem_u32(&Vs[nb][key][c8]), g_v + ((size_t)(b * NN + k0 + key)) * CC + c8);
            }
            CP_COMMIT();
            asm volatile("cp.async.wait_group 1;" ::: "memory");
        } else {
            asm volatile("cp.async.wait_group 0;" ::: "memory");
        }
        __syncthreads();
        int bs = t & 1;

        uint32_t aK = smem_u32(&Ks[bs][lane & 15][0]);
        uint32_t aV = smem_u32(&Vs[bs][lane & 15][(lane >> 4) * 8]);
        #pragma unroll 2
        for (int kc = 0; kc < 8; kc++) {
            uint32_t kb0, kb1;
            asm volatile("ldmatrix.sync.aligned.m8n8.x2.shared.b16 {%0,%1}, [%2];"
                         : "=r"(kb0), "=r"(kb1) : "r"(aK));
            uint32_t vb[8][2];
            #pragma unroll
            for (int m = 0; m < 4; m++) {
                asm volatile("ldmatrix.sync.aligned.m8n8.x4.trans.shared.b16 {%0,%1,%2,%3}, [%4];"
                             : "=r"(vb[2 * m][0]), "=r"(vb[2 * m][1]),
                               "=r"(vb[2 * m + 1][0]), "=r"(vb[2 * m + 1][1])
                             : "r"(aV + m * 32));
            }
            aK += 16 * 16;
            aV += 16 * 144;
            #pragma unroll
            for (int i = 0; i < 2; i++) {
                float s0[4] = {0.f, 0.f, 0.f, 0.f}, s1[4] = {0.f, 0.f, 0.f, 0.f};
                MMA_BF16_K8(s0, qa[i][0], qa[i][1], kb0);
                MMA_BF16_K8(s1, qa[i][0], qa[i][1], kb1);
                uint32_t pa0, pa1, pa2, pa3;
                asm("cvt.rn.f16x2.f32 %0, %1, %2;" : "=r"(pa0) : "f"(s0[1]), "f"(s0[0]));
                asm("cvt.rn.f16x2.f32 %0, %1, %2;" : "=r"(pa1) : "f"(s0[3]), "f"(s0[2]));
                asm("cvt.rn.f16x2.f32 %0, %1, %2;" : "=r"(pa2) : "f"(s1[1]), "f"(s1[0]));
                asm("cvt.rn.f16x2.f32 %0, %1, %2;" : "=r"(pa3) : "f"(s1[3]), "f"(s1[2]));
                asm("ex2.approx.f16x2 %0, %0;" : "+r"(pa0));
                asm("ex2.approx.f16x2 %0, %0;" : "+r"(pa1));
                asm("ex2.approx.f16x2 %0, %0;" : "+r"(pa2));
                asm("ex2.approx.f16x2 %0, %0;" : "+r"(pa3));
                #pragma unroll
                for (int j = 0; j < 8; j++)
                    MMA_F16(d2[i][j], pa0, pa1, pa2, pa3, vb[j][0], vb[j][1]);
                MMA_F16(d2[i][8], pa0, pa1, pa2, pa3, vbO0, vbO1);
            }
        }
        __syncthreads();
    }

    int bs2 = b * KSPL + sp;
    uint32_t* pD = g_pDh + (size_t)bs2 * (CC / 2) * NN;
    #pragma unroll
    for (int i = 0; i < 2; i++) {
        int q0 = qrow + i * 16 + g, q1 = q0 + 8;
        if (tp == 0) {
            g_pl[(size_t)bs2 * NN + q0] = d2[i][8][0];
            g_pl[(size_t)bs2 * NN + q1] = d2[i][8][2];
        }
        #pragma unroll
        for (int j = 0; j < 8; j++) {
            int cp = j * 4 + tp;
            uint32_t w0, w1;
            asm("cvt.rn.f16x2.f32 %0, %1, %2;" : "=r"(w0) : "f"(d2[i][j][1]), "f"(d2[i][j][0]));
            asm("cvt.rn.f16x2.f32 %0, %1, %2;" : "=r"(w1) : "f"(d2[i][j][3]), "f"(d2[i][j][2]));
            pD[(size_t)cp * NN + q0] = w0;
            pD[(size_t)cp * NN + q1] = w1;
        }
    }
}

// ---------------- Stage D: combine splits + epilogue ----------------------------
__global__ void __launch_bounds__(256) k_comb(const float* __restrict__ gamma,
                                              const float* __restrict__ cnn,
                                              float* __restrict__ out) {
    int b = blockIdx.y;
    int q = blockIdx.x * 128 + (threadIdx.x & 127);
    int cp0 = (threadIdx.x >> 7) * 16;
    float l = 0.f;
    #pragma unroll
    for (int s = 0; s < KSPL; s++) l += g_pl[(size_t)(b * KSPL + s) * NN + q];
    float inv = gamma[0] / l;
    const float* cb = cnn + (size_t)b * CC * NN + q;
    float* ob = out + (size_t)b * CC * NN + q;
    #pragma unroll 4
    for (int i = 0; i < 16; i++) {
        int cp = cp0 + i;
        float a0 = 0.f, a1 = 0.f;
        #pragma unroll
        for (int s = 0; s < KSPL; s++) {
            uint32_t v = g_pDh[((size_t)(b * KSPL + s) * (CC / 2) + cp) * NN + q];
            float2 f = __half22float2(*reinterpret_cast<__half2*>(&v));
            a0 += f.x; a1 += f.y;
        }
        ob[(size_t)(2 * cp) * NN]     = a0 * inv + cb[(size_t)(2 * cp) * NN];
        ob[(size_t)(2 * cp + 1) * NN] = a1 * inv + cb[(size_t)(2 * cp + 1) * NN];
    }
}

// ---------------- launch ---------------------------------------------------------
extern "C" void kernel_launch(void* const* d_in, const int* in_sizes, int n_in,
                              void* d_out, int out_size) {
    const float* cnn   = (const float*)d_in[0];
    const float* vit   = (const float*)d_in[1];
    const float* Wq    = (const float*)d_in[2];
    const float* bq    = (const float*)d_in[3];
    const float* Wk    = (const float*)d_in[4];
    const float* bk    = (const float*)d_in[5];
    const float* Wv    = (const float*)d_in[6];
    const float* bv    = (const float*)d_in[7];
    const float* gamma = (const float*)d_in[8];
    const float* gcnn  = (const float*)d_in[9];
    const float* gvit  = (const float*)d_in[10];
    float* out = (float*)d_out;

    k_gram <<<dim3(NCHUNK, NIMG), 256>>>(cnn, vit);
    k_prep <<<NIMG, 256>>>(Wq, Wk, Wv, gcnn, gvit);
    k_qkv  <<<dim3(NN / 32, BB), 192>>>(cnn, vit, bq, bk, bv);
    k_attn <<<dim3(NN / 256, BB, KSPL), 256>>>();
    k_comb <<<dim3(NN / 128, BB), 256>>>(gamma, cnn, out);
}

// round 15
// speedup vs baseline: 1.2811x; 1.0222x over previous
#include <cuda_runtime.h>
#include <cuda_bf16.h>
#include <cuda_fp16.h>
#include <cstdint>

// Problem constants
#define BB 4
#define CC 64
#define NN 4096
#define C8V 8
#define NIMG 8
#define NCHUNK 32
#define KSPL 4
#define NTILE (NN / KSPL / 128)
#define RLN2 1.4426950408889634f

// ---------------- scratch ----------------------------------------------------
__device__ float g_gpart[NCHUNK * NIMG * CC * CC];
__device__ float g_WqT[BB * CC * C8V];             // [b][c][o], prescaled by 1/ln2
__device__ float g_WkT[BB * CC * C8V];             // [b][c][o]
__device__ float g_WvTe[BB * CC * CC];             // [b][c][o]
__device__ __nv_bfloat16 g_qb[BB * NN * C8V];      // [b][n][8] (prescaled 1/ln2)
__device__ __nv_bfloat16 g_kb[BB * NN * C8V];      // [b][n][8]
__device__ __half        g_v [BB * NN * CC];       // [b][n][c]
__device__ uint32_t g_pDh[BB * KSPL * (CC / 2) * NN];  // packed f16x2 partials
__device__ float g_pl[BB * KSPL * NN];             // partial row-sums [b][s][q]

__device__ __forceinline__ uint32_t smem_u32(const void* p) {
    uint32_t a;
    asm("{ .reg .u64 t; cvta.to.shared.u64 t, %1; cvt.u32.u64 %0, t; }" : "=r"(a) : "l"(p));
    return a;
}

#define MMA_BF16_K8(d, a0, a1, b0)                                                 \
    asm volatile("mma.sync.aligned.m16n8k8.row.col.f32.bf16.bf16.f32 "             \
        "{%0,%1,%2,%3}, {%4,%5}, {%6}, {%0,%1,%2,%3};"                             \
        : "+f"((d)[0]), "+f"((d)[1]), "+f"((d)[2]), "+f"((d)[3])                   \
        : "r"(a0), "r"(a1), "r"(b0))

#define MMA_F16(d, a0, a1, a2, a3, b0, b1)                                         \
    asm volatile("mma.sync.aligned.m16n8k16.row.col.f32.f16.f16.f32 "              \
        "{%0,%1,%2,%3}, {%4,%5,%6,%7}, {%8,%9}, {%0,%1,%2,%3};"                    \
        : "+f"((d)[0]), "+f"((d)[1]), "+f"((d)[2]), "+f"((d)[3])                   \
        : "r"(a0), "r"(a1), "r"(a2), "r"(a3), "r"(b0), "r"(b1))

#define MMA_BF16_K16(d, a0, a1, a2, a3, b0, b1)                                    \
    asm volatile("mma.sync.aligned.m16n8k16.row.col.f32.bf16.bf16.f32 "            \
        "{%0,%1,%2,%3}, {%4,%5,%6,%7}, {%8,%9}, {%0,%1,%2,%3};"                    \
        : "+f"((d)[0]), "+f"((d)[1]), "+f"((d)[2]), "+f"((d)[3])                   \
        : "r"(a0), "r"(a1), "r"(a2), "r"(a3), "r"(b0), "r"(b1))

#define LDSM_X4(r0, r1, r2, r3, addr)                                              \
    asm volatile("ldmatrix.sync.aligned.m8n8.x4.shared.b16 {%0,%1,%2,%3}, [%4];"   \
                 : "=r"(r0), "=r"(r1), "=r"(r2), "=r"(r3) : "r"(addr))

#define LDSM_X4T(r0, r1, r2, r3, addr)                                             \
    asm volatile("ldmatrix.sync.aligned.m8n8.x4.trans.shared.b16 {%0,%1,%2,%3}, [%4];" \
                 : "=r"(r0), "=r"(r1), "=r"(r2), "=r"(r3) : "r"(addr))

#define CP16(dst, src) asm volatile("cp.async.cg.shared.global [%0], [%1], 16;" :: "r"(dst), "l"(src) : "memory")
#define CP_COMMIT()    asm volatile("cp.async.commit_group;" ::: "memory")

// ---------------- Stage A1: gram partials via tensor cores (split-bf16) --------
#define GROWS 144
__global__ void __launch_bounds__(256) k_gram(const float* __restrict__ cnn,
                                              const float* __restrict__ vit) {
    int chunk = blockIdx.x, img = blockIdx.y;
    const float* x = (img < BB) ? (cnn + img * CC * NN) : (vit + (img - BB) * CC * NN);
    __shared__ __align__(16) __nv_bfloat16 xh[CC][GROWS];
    __shared__ __align__(16) __nv_bfloat16 xl[CC][GROWS];
    int tid = threadIdx.x;
    int n0 = chunk * 128;

    for (int i = tid; i < CC * 64; i += 256) {
        int c = i >> 6, j2 = (i & 63) * 2;
        float2 v = *(const float2*)(x + c * NN + n0 + j2);
        __nv_bfloat16 h0 = __float2bfloat16(v.x);
        __nv_bfloat16 h1 = __float2bfloat16(v.y);
        __nv_bfloat16 l0 = __float2bfloat16(v.x - __bfloat162float(h0));
        __nv_bfloat16 l1 = __float2bfloat16(v.y - __bfloat162float(h1));
        uint32_t hp = ((uint32_t)__bfloat16_as_ushort(h1) << 16) | __bfloat16_as_ushort(h0);
        uint32_t lp = ((uint32_t)__bfloat16_as_ushort(l1) << 16) | __bfloat16_as_ushort(l0);
        *(uint32_t*)&xh[c][j2] = hp;
        *(uint32_t*)&xl[c][j2] = lp;
    }
    __syncthreads();

    int w = tid >> 5, lane = tid & 31;
    int g = lane >> 2, tp = lane & 3;
    int mi = w & 3, nh = w >> 2;
    int m0 = mi * 16, cj0 = nh * 32;

    uint32_t aAh = smem_u32(&xh[m0 + (lane & 15)][(lane >> 4) * 8]);
    uint32_t aAl = smem_u32(&xl[m0 + (lane & 15)][(lane >> 4) * 8]);
    uint32_t aBh = smem_u32(&xh[cj0 + ((lane >> 4) & 1) * 8 + (lane & 7)][((lane >> 3) & 1) * 8]);
    uint32_t aBl = smem_u32(&xl[cj0 + ((lane >> 4) & 1) * 8 + (lane & 7)][((lane >> 3) & 1) * 8]);
    const uint32_t BOFF2 = 16u * (GROWS * 2);

    float d[4][4];
    #pragma unroll
    for (int b2 = 0; b2 < 4; b2++)
        #pragma unroll
        for (int r = 0; r < 4; r++) d[b2][r] = 0.f;

    #pragma unroll
    for (int ks = 0; ks < 8; ks++) {
        uint32_t ah0, ah1, ah2, ah3, al0, al1, al2, al3;
        LDSM_X4(ah0, ah1, ah2, ah3, aAh);
        LDSM_X4(al0, al1, al2, al3, aAl);
        uint32_t bh[8], bl[8];
        LDSM_X4(bh[0], bh[1], bh[2], bh[3], aBh);
        LDSM_X4(bh[4], bh[5], bh[6], bh[7], aBh + BOFF2);
        LDSM_X4(bl[0], bl[1], bl[2], bl[3], aBl);
        LDSM_X4(bl[4], bl[5], bl[6], bl[7], aBl + BOFF2);
        aAh += 32; aAl += 32; aBh += 32; aBl += 32;
        #pragma unroll
        for (int b2 = 0; b2 < 4; b2++) {
            MMA_BF16_K16(d[b2], ah0, ah1, ah2, ah3, bh[2 * b2], bh[2 * b2 + 1]);
            MMA_BF16_K16(d[b2], ah0, ah1, ah2, ah3, bl[2 * b2], bl[2 * b2 + 1]);
            MMA_BF16_K16(d[b2], al0, al1, al2, al3, bh[2 * b2], bh[2 * b2 + 1]);
        }
    }

    float* outp = g_gpart + (chunk * NIMG + img) * CC * CC;
    #pragma unroll
    for (int b2 = 0; b2 < 4; b2++) {
        int col = cj0 + b2 * 8 + 2 * tp;
        *(float2*)&outp[(m0 + g) * CC + col]     = make_float2(d[b2][0], d[b2][1]);
        *(float2*)&outp[(m0 + g + 8) * CC + col] = make_float2(d[b2][2], d[b2][3]);
    }
}

// ---------------- Stage A2: reduce + softmax + effective-weight compose --------
__global__ void k_prep(const float* __restrict__ Wq, const float* __restrict__ Wk,
                       const float* __restrict__ Wv,
                       const float* __restrict__ gcnn, const float* __restrict__ gvit) {
    int img = blockIdx.x;
    int tid = threadIdx.x;
    __shared__ __align__(16) float As[CC * CC];
    __shared__ __align__(16) float Wvs[CC * 68];
    __shared__ float Wqs[CC * C8V];

    for (int p = tid; p < CC * CC; p += 256) {
        float s = 0.f;
        #pragma unroll
        for (int ch = 0; ch < NCHUNK; ch++)
            s += g_gpart[(ch * NIMG + img) * CC * CC + p];
        As[p] = s;
    }
    __syncthreads();

    {
        int r = tid >> 2, l4 = tid & 3;
        float m = -1e30f;
        for (int d = l4; d < CC; d += 4) m = fmaxf(m, -As[r * CC + d]);
        m = fmaxf(m, __shfl_xor_sync(0xffffffffu, m, 1));
        m = fmaxf(m, __shfl_xor_sync(0xffffffffu, m, 2));
        float s = 0.f;
        for (int d = l4; d < CC; d += 4) s += __expf(-As[r * CC + d] - m);
        s += __shfl_xor_sync(0xffffffffu, s, 1);
        s += __shfl_xor_sync(0xffffffffu, s, 2);
        float inv = 1.f / s;
        for (int d = l4; d < CC; d += 4)
            As[r * CC + d] = __expf(-As[r * CC + d] - m) * inv;
    }

    const float* Wsm = (img < BB) ? Wq : Wk;
    for (int i = tid; i < C8V * CC; i += 256)
        Wqs[(i & 63) * C8V + (i >> 6)] = Wsm[i];
    if (img >= BB) {
        for (int i = tid; i < CC * CC; i += 256)
            Wvs[(i & 63) * 68 + (i >> 6)] = Wv[i];
    }
    __syncthreads();

    if (img < BB) {
        float g = gcnn[0];
        for (int p = tid; p < CC * C8V; p += 256) {
            int d = p >> 3, o = p & 7;
            float s = 0.f;
            #pragma unroll 4
            for (int c = 0; c < CC; c++) s += Wqs[c * C8V + o] * As[c * CC + d];
            g_WqT[img * CC * C8V + d * C8V + o] = (Wqs[d * C8V + o] + g * s) * RLN2;
        }
    } else {
        int b = img - BB;
        float g = gvit[0];
        for (int p = tid; p < CC * C8V; p += 256) {
            int d = p >> 3, o = p & 7;
            float s = 0.f;
            #pragma unroll 4
            for (int c = 0; c < CC; c++) s += Wqs[c * C8V + o] * As[c * CC + d];
            g_WkT[b * CC * C8V + d * C8V + o] = Wqs[d * C8V + o] + g * s;
        }
        int tx = tid & 15, ty = tid >> 4;
        int o0 = tx * 4, d0 = ty * 4;
        float acc[4][4];
        #pragma unroll
        for (int i = 0; i < 4; i++)
            #pragma unroll
            for (int j = 0; j < 4; j++) acc[i][j] = 0.f;
        for (int c = 0; c < CC; c++) {
            float4 a = *(const float4*)&As[c * CC + d0];
            float4 wv = *(const float4*)&Wvs[c * 68 + o0];
            float ar[4] = {a.x, a.y, a.z, a.w};
            float wr[4] = {wv.x, wv.y, wv.z, wv.w};
            #pragma unroll
            for (int i = 0; i < 4; i++)
                #pragma unroll
                for (int j = 0; j < 4; j++) acc[i][j] += ar[i] * wr[j];
        }
        #pragma unroll
        for (int i = 0; i < 4; i++) {
            float4 wd = *(const float4*)&Wvs[(d0 + i) * 68 + o0];
            float4 o = make_float4(wd.x + g * acc[i][0], wd.y + g * acc[i][1],
                                   wd.z + g * acc[i][2], wd.w + g * acc[i][3]);
            *(float4*)&g_WvTe[b * CC * CC + (d0 + i) * CC + o0] = o;
        }
    }
}

// ---------------- Stage B: tensor-core fused q/k/v projections -----------------
// grid (32, 4), 256 threads (8 warps x 16 n rows). A = x^T (ldmatrix.trans from
// [c][n] smem), B = W^T ([c][o] smem, ldmatrix.trans). Plain bf16 operands.
#define XROWS 136   // 272B rows
__global__ void __launch_bounds__(256) k_qkv(const float* __restrict__ cnn,
                                             const float* __restrict__ vit,
                                             const float* __restrict__ bq,
                                             const float* __restrict__ bk,
                                             const float* __restrict__ bv) {
    int chunk = blockIdx.x, b = blockIdx.y;
    int tid = threadIdx.x;
    int n0 = chunk * 128;

    __shared__ __align__(16) __nv_bfloat16 xc[CC][XROWS];   // cnn chunk [c][n]
    __shared__ __align__(16) __nv_bfloat16 xv[CC][XROWS];   // vit chunk [c][n]
    __shared__ __align__(16) __nv_bfloat16 Wvs[CC][72];     // Wv_eff^T [c][o]
    __shared__ __align__(16) __nv_bfloat16 Wqks[CC][24];    // [c][o: 0-7 q, 8-15 k]

    const float* pc = cnn + (size_t)b * CC * NN;
    const float* pv = vit + (size_t)b * CC * NN;
    for (int i = tid; i < CC * 64; i += 256) {
        int c = i >> 6, j2 = (i & 63) * 2;
        float2 vc = *(const float2*)(pc + c * NN + n0 + j2);
        float2 vv = *(const float2*)(pv + c * NN + n0 + j2);
        *(uint32_t*)&xc[c][j2] = ((uint32_t)__bfloat16_as_ushort(__float2bfloat16(vc.y)) << 16)
                               | __bfloat16_as_ushort(__float2bfloat16(vc.x));
        *(uint32_t*)&xv[c][j2] = ((uint32_t)__bfloat16_as_ushort(__float2bfloat16(vv.y)) << 16)
                               | __bfloat16_as_ushort(__float2bfloat16(vv.x));
    }
    const float* wv = g_WvTe + b * CC * CC;
    for (int i = tid; i < CC * 32; i += 256) {
        int c = i >> 5, o2 = (i & 31) * 2;
        float2 v = *(const float2*)(wv + c * CC + o2);
        *(uint32_t*)&Wvs[c][o2] = ((uint32_t)__bfloat16_as_ushort(__float2bfloat16(v.y)) << 16)
                                | __bfloat16_as_ushort(__float2bfloat16(v.x));
    }
    for (int i = tid; i < CC * 8; i += 256) {
        int c = i >> 3, o2 = (i & 7) * 2;
        float2 v;
        if (o2 < 8) v = *(const float2*)(g_WqT + b * CC * C8V + c * C8V + o2);
        else        v = *(const float2*)(g_WkT + b * CC * C8V + c * C8V + (o2 - 8));
        *(uint32_t*)&Wqks[c][o2] = ((uint32_t)__bfloat16_as_ushort(__float2bfloat16(v.y)) << 16)
                                 | __bfloat16_as_ushort(__float2bfloat16(v.x));
    }
    __syncthreads();

    int w = tid >> 5, lane = tid & 31;
    int g = lane >> 2, tp = lane & 3;
    int m0 = w * 16;

    // A ldsm.trans addresses (per kstep +16 c rows)
    uint32_t aC = smem_u32(&xc[(lane >> 4) * 8 + (lane & 7)][m0 + ((lane >> 3) & 1) * 8]);
    uint32_t aV = smem_u32(&xv[(lane >> 4) * 8 + (lane & 7)][m0 + ((lane >> 3) & 1) * 8]);
    // B ldsm.trans addresses (weights)
    uint32_t aWv  = smem_u32(&Wvs[((lane >> 3) & 1) * 8 + (lane & 7)][(lane >> 4) * 8]);
    uint32_t aWqk = smem_u32(&Wqks[((lane >> 3) & 1) * 8 + (lane & 7)][(lane >> 4) * 8]);

    float dv[8][4], dq[4], dk[4];
    #pragma unroll
    for (int j = 0; j < 8; j++) {
        dv[j][0] = bv[j * 8 + 2 * tp];
        dv[j][1] = bv[j * 8 + 2 * tp + 1];
        dv[j][2] = dv[j][0];
        dv[j][3] = dv[j][1];
    }
    dq[0] = bq[2 * tp] * RLN2; dq[1] = bq[2 * tp + 1] * RLN2; dq[2] = dq[0]; dq[3] = dq[1];
    dk[0] = bk[2 * tp];        dk[1] = bk[2 * tp + 1];        dk[2] = dk[0]; dk[3] = dk[1];

    #pragma unroll
    for (int ks = 0; ks < 4; ks++) {
        uint32_t ac0, ac1, ac2, ac3, av0, av1, av2, av3;
        LDSM_X4T(ac0, ac1, ac2, ac3, aC);
        LDSM_X4T(av0, av1, av2, av3, aV);
        uint32_t bwv[8][2];
        #pragma unroll
        for (int m = 0; m < 4; m++) {
            LDSM_X4T(bwv[2 * m][0], bwv[2 * m][1], bwv[2 * m + 1][0], bwv[2 * m + 1][1],
                     aWv + m * 32);
        }
        uint32_t bq0, bq1, bk0, bk1;
        LDSM_X4T(bq0, bq1, bk0, bk1, aWqk);
        aC += 16u * (XROWS * 2); aV += 16u * (XROWS * 2);
        aWv += 16u * (72 * 2);   aWqk += 16u * (24 * 2);

        #pragma unroll
        for (int j = 0; j < 8; j++)
            MMA_BF16_K16(dv[j], av0, av1, av2, av3, bwv[j][0], bwv[j][1]);
        MMA_BF16_K16(dq, ac0, ac1, ac2, ac3, bq0, bq1);
        MMA_BF16_K16(dk, av0, av1, av2, av3, bk0, bk1);
    }

    // epilogue
    int ng0 = n0 + m0 + g, ng1 = ng0 + 8;
    __half* vd0 = g_v + ((size_t)(b * NN + ng0)) * CC + 2 * tp;
    __half* vd1 = g_v + ((size_t)(b * NN + ng1)) * CC + 2 * tp;
    #pragma unroll
    for (int j = 0; j < 8; j++) {
        uint32_t u0, u1;
        asm("cvt.rn.f16x2.f32 %0, %1, %2;" : "=r"(u0) : "f"(dv[j][1]), "f"(dv[j][0]));
        asm("cvt.rn.f16x2.f32 %0, %1, %2;" : "=r"(u1) : "f"(dv[j][3]), "f"(dv[j][2]));
        *(uint32_t*)(vd0 + j * 8) = u0;
        *(uint32_t*)(vd1 + j * 8) = u1;
    }
    uint32_t uq0, uq1, uk0, uk1;
    asm("cvt.rn.bf16x2.f32 %0, %1, %2;" : "=r"(uq0) : "f"(dq[1]), "f"(dq[0]));
    asm("cvt.rn.bf16x2.f32 %0, %1, %2;" : "=r"(uq1) : "f"(dq[3]), "f"(dq[2]));
    asm("cvt.rn.bf16x2.f32 %0, %1, %2;" : "=r"(uk0) : "f"(dk[1]), "f"(dk[0]));
    asm("cvt.rn.bf16x2.f32 %0, %1, %2;" : "=r"(uk1) : "f"(dk[3]), "f"(dk[2]));
    *(uint32_t*)(g_qb + ((size_t)(b * NN + ng0)) * 8 + 2 * tp) = uq0;
    *(uint32_t*)(g_qb + ((size_t)(b * NN + ng1)) * 8 + 2 * tp) = uq1;
    *(uint32_t*)(g_kb + ((size_t)(b * NN + ng0)) * 8 + 2 * tp) = uk0;
    *(uint32_t*)(g_kb + ((size_t)(b * NN + ng1)) * 8 + 2 * tp) = uk1;
}

// ---------------- Stage C: mma attention (R12 best config, unchanged) ----------
__global__ void __launch_bounds__(256, 2) k_attn() {
    int qt = blockIdx.x, b = blockIdx.y, sp = blockIdx.z;
    int tid = threadIdx.x;
    int w = tid >> 5, lane = tid & 31;
    int g = lane >> 2, tp = lane & 3;
    int kbase = sp * (NN / KSPL);

    __shared__ __align__(16) __nv_bfloat16 Ks[2][128][8];
    __shared__ __align__(16) __half        Vs[2][128][72];

    for (int i = tid; i < 2 * 128; i += 256) {
        uint4 z; z.x = 0x00003C00u; z.y = 0; z.z = 0; z.w = 0;
        *(uint4*)&Vs[i >> 7][i & 127][64] = z;
    }
    __syncthreads();

    uint32_t vbO0, vbO1;
    asm volatile("ldmatrix.sync.aligned.m8n8.x2.trans.shared.b16 {%0,%1}, [%2];"
                 : "=r"(vbO0), "=r"(vbO1) : "r"(smem_u32(&Vs[0][lane & 15][64])));

    int qrow = qt * 256 + w * 32;
    uint32_t qa[2][2];
    #pragma unroll
    for (int i = 0; i < 2; i++) {
        qa[i][0] = *(const uint32_t*)(g_qb + ((size_t)(b * NN + qrow + i * 16 + g)) * 8 + 2 * tp);
        qa[i][1] = *(const uint32_t*)(g_qb + ((size_t)(b * NN + qrow + i * 16 + g + 8)) * 8 + 2 * tp);
    }

    float d2[2][9][4];
    #pragma unroll
    for (int i = 0; i < 2; i++)
        #pragma unroll
        for (int j = 0; j < 9; j++)
            #pragma unroll
            for (int r = 0; r < 4; r++) d2[i][j][r] = 0.f;

    {
        if (tid < 128) CP16(smem_u32(&Ks[0][tid][0]), g_kb + ((size_t)(b * NN + kbase + tid)) * 8);
        #pragma unroll
        for (int i2 = 0; i2 < 4; i2++) {
            int idx = tid + i2 * 256, key = idx >> 3, c8 = (idx & 7) * 8;
            CP16(smem_u32(&Vs[0][key][c8]), g_v + ((size_t)(b * NN + kbase + key)) * CC + c8);
        }
        CP_COMMIT();
    }

    for (int t = 0; t < NTILE; t++) {
        if (t + 1 < NTILE) {
            int nb = (t + 1) & 1, k0 = kbase + (t + 1) * 128;
            if (tid < 128) CP16(smem_u32(&Ks[nb][tid][0]), g_kb + ((size_t)(b * NN + k0 + tid)) * 8);
            #pragma unroll
            for (int i2 = 0; i2 < 4; i2++) {
                int idx = tid + i2 * 256, key = idx >> 3, c8 = (idx & 7) * 8;
                CP16(smem_u32(&Vs[nb][key][c8]), g_v + ((size_t)(b * NN + k0 + key)) * CC + c8);
            }
            CP_COMMIT();
            asm volatile("cp.async.wait_group 1;" ::: "memory");
        } else {
            asm volatile("cp.async.wait_group 0;" ::: "memory");
        }
        __syncthreads();
        int bs = t & 1;

        uint32_t aK = smem_u32(&Ks[bs][lane & 15][0]);
        uint32_t aV = smem_u32(&Vs[bs][lane & 15][(lane >> 4) * 8]);
        #pragma unroll 2
        for (int kc = 0; kc < 8; kc++) {
            uint32_t kb0, kb1;
            asm volatile("ldmatrix.sync.aligned.m8n8.x2.shared.b16 {%0,%1}, [%2];"
                         : "=r"(kb0), "=r"(kb1) : "r"(aK));
            uint32_t vb[8][2];
            #pragma unroll
            for (int m = 0; m < 4; m++) {
                asm volatile("ldmatrix.sync.aligned.m8n8.x4.trans.shared.b16 {%0,%1,%2,%3}, [%4];"
                             : "=r"(vb[2 * m][0]), "=r"(vb[2 * m][1]),
                               "=r"(vb[2 * m + 1][0]), "=r"(vb[2 * m + 1][1])
                             : "r"(aV + m * 32));
            }
            aK += 16 * 16;
            aV += 16 * 144;
            #pragma unroll
            for (int i = 0; i < 2; i++) {
                float s0[4] = {0.f, 0.f, 0.f, 0.f}, s1[4] = {0.f, 0.f, 0.f, 0.f};
                MMA_BF16_K8(s0, qa[i][0], qa[i][1], kb0);
                MMA_BF16_K8(s1, qa[i][0], qa[i][1], kb1);
                uint32_t pa0, pa1, pa2, pa3;
                asm("cvt.rn.f16x2.f32 %0, %1, %2;" : "=r"(pa0) : "f"(s0[1]), "f"(s0[0]));
                asm("cvt.rn.f16x2.f32 %0, %1, %2;" : "=r"(pa1) : "f"(s0[3]), "f"(s0[2]));
                asm("cvt.rn.f16x2.f32 %0, %1, %2;" : "=r"(pa2) : "f"(s1[1]), "f"(s1[0]));
                asm("cvt.rn.f16x2.f32 %0, %1, %2;" : "=r"(pa3) : "f"(s1[3]), "f"(s1[2]));
                asm("ex2.approx.f16x2 %0, %0;" : "+r"(pa0));
                asm("ex2.approx.f16x2 %0, %0;" : "+r"(pa1));
                asm("ex2.approx.f16x2 %0, %0;" : "+r"(pa2));
                asm("ex2.approx.f16x2 %0, %0;" : "+r"(pa3));
                #pragma unroll
                for (int j = 0; j < 8; j++)
                    MMA_F16(d2[i][j], pa0, pa1, pa2, pa3, vb[j][0], vb[j][1]);
                MMA_F16(d2[i][8], pa0, pa1, pa2, pa3, vbO0, vbO1);
            }
        }
        __syncthreads();
    }

    int bs2 = b * KSPL + sp;
    uint32_t* pD = g_pDh + (size_t)bs2 * (CC / 2) * NN;
    #pragma unroll
    for (int i = 0; i < 2; i++) {
        int q0 = qrow + i * 16 + g, q1 = q0 + 8;
        if (tp == 0) {
            g_pl[(size_t)bs2 * NN + q0] = d2[i][8][0];
            g_pl[(size_t)bs2 * NN + q1] = d2[i][8][2];
        }
        #pragma unroll
        for (int j = 0; j < 8; j++) {
            int cp = j * 4 + tp;
            uint32_t w0, w1;
            asm("cvt.rn.f16x2.f32 %0, %1, %2;" : "=r"(w0) : "f"(d2[i][j][1]), "f"(d2[i][j][0]));
            asm("cvt.rn.f16x2.f32 %0, %1, %2;" : "=r"(w1) : "f"(d2[i][j][3]), "f"(d2[i][j][2]));
            pD[(size_t)cp * NN + q0] = w0;
            pD[(size_t)cp * NN + q1] = w1;
        }
    }
}

// ---------------- Stage D: combine splits + epilogue ----------------------------
__global__ void __launch_bounds__(256) k_comb(const float* __restrict__ gamma,
                                              const float* __restrict__ cnn,
                                              float* __restrict__ out) {
    int b = blockIdx.y;
    int q = blockIdx.x * 128 + (threadIdx.x & 127);
    int cp0 = (threadIdx.x >> 7) * 16;
    float l = 0.f;
    #pragma unroll
    for (int s = 0; s < KSPL; s++) l += g_pl[(size_t)(b * KSPL + s) * NN + q];
    float inv = gamma[0] / l;
    const float* cb = cnn + (size_t)b * CC * NN + q;
    float* ob = out + (size_t)b * CC * NN + q;
    #pragma unroll 4
    for (int i = 0; i < 16; i++) {
        int cp = cp0 + i;
        float a0 = 0.f, a1 = 0.f;
        #pragma unroll
        for (int s = 0; s < KSPL; s++) {
            uint32_t v = g_pDh[((size_t)(b * KSPL + s) * (CC / 2) + cp) * NN + q];
            float2 f = __half22float2(*reinterpret_cast<__half2*>(&v));
            a0 += f.x; a1 += f.y;
        }
        ob[(size_t)(2 * cp) * NN]     = a0 * inv + cb[(size_t)(2 * cp) * NN];
        ob[(size_t)(2 * cp + 1) * NN] = a1 * inv + cb[(size_t)(2 * cp + 1) * NN];
    }
}

// ---------------- launch ---------------------------------------------------------
extern "C" void kernel_launch(void* const* d_in, const int* in_sizes, int n_in,
                              void* d_out, int out_size) {
    const float* cnn   = (const float*)d_in[0];
    const float* vit   = (const float*)d_in[1];
    const float* Wq    = (const float*)d_in[2];
    const float* bq    = (const float*)d_in[3];
    const float* Wk    = (const float*)d_in[4];
    const float* bk    = (const float*)d_in[5];
    const float* Wv    = (const float*)d_in[6];
    const float* bv    = (const float*)d_in[7];
    const float* gamma = (const float*)d_in[8];
    const float* gcnn  = (const float*)d_in[9];
    const float* gvit  = (const float*)d_in[10];
    float* out = (float*)d_out;

    k_gram <<<dim3(NCHUNK, NIMG), 256>>>(cnn, vit);
    k_prep <<<NIMG, 256>>>(Wq, Wk, Wv, gcnn, gvit);
    k_qkv  <<<dim3(NN / 128, BB), 256>>>(cnn, vit, bq, bk, bv);
    k_attn <<<dim3(NN / 256, BB, KSPL), 256>>>();
    k_comb <<<dim3(NN / 128, BB), 256>>>(gamma, cnn, out);
}

// round 16
// speedup vs baseline: 1.4668x; 1.1450x over previous
#include <cuda_runtime.h>
#include <cuda_bf16.h>
#include <cuda_fp16.h>
#include <cstdint>

// Problem constants
#define BB 4
#define CC 64
#define NN 4096
#define C8V 8
#define NIMG 8
#define NCHUNK 16
#define KSPL 4
#define NTILE (NN / KSPL / 128)
#define RLN2 1.4426950408889634f

// ---------------- scratch ----------------------------------------------------
__device__ float g_gpart[NCHUNK * NIMG * CC * CC];
__device__ __nv_bfloat16 g_Wqkb[BB * CC * 16];     // [b][c][o]: 0-7 q (RLN2-scaled), 8-15 k
__device__ __nv_bfloat16 g_Wvb[BB * CC * CC];      // [b][c][o]
__device__ __nv_bfloat16 g_qb[BB * NN * C8V];      // [b][n][8] (prescaled 1/ln2)
__device__ __nv_bfloat16 g_kb[BB * NN * C8V];      // [b][n][8]
__device__ __half        g_v [BB * NN * CC];       // [b][n][c]
__device__ uint32_t g_pDh[BB * KSPL * (CC / 2) * NN];  // packed f16x2 partials
__device__ float g_pl[BB * KSPL * NN];             // partial row-sums [b][s][q]

__device__ __forceinline__ uint32_t smem_u32(const void* p) {
    uint32_t a;
    asm("{ .reg .u64 t; cvta.to.shared.u64 t, %1; cvt.u32.u64 %0, t; }" : "=r"(a) : "l"(p));
    return a;
}

#define MMA_BF16_K8(d, a0, a1, b0)                                                 \
    asm volatile("mma.sync.aligned.m16n8k8.row.col.f32.bf16.bf16.f32 "             \
        "{%0,%1,%2,%3}, {%4,%5}, {%6}, {%0,%1,%2,%3};"                             \
        : "+f"((d)[0]), "+f"((d)[1]), "+f"((d)[2]), "+f"((d)[3])                   \
        : "r"(a0), "r"(a1), "r"(b0))

#define MMA_F16(d, a0, a1, a2, a3, b0, b1)                                         \
    asm volatile("mma.sync.aligned.m16n8k16.row.col.f32.f16.f16.f32 "              \
        "{%0,%1,%2,%3}, {%4,%5,%6,%7}, {%8,%9}, {%0,%1,%2,%3};"                    \
        : "+f"((d)[0]), "+f"((d)[1]), "+f"((d)[2]), "+f"((d)[3])                   \
        : "r"(a0), "r"(a1), "r"(a2), "r"(a3), "r"(b0), "r"(b1))

#define MMA_BF16_K16(d, a0, a1, a2, a3, b0, b1)                                    \
    asm volatile("mma.sync.aligned.m16n8k16.row.col.f32.bf16.bf16.f32 "            \
        "{%0,%1,%2,%3}, {%4,%5,%6,%7}, {%8,%9}, {%0,%1,%2,%3};"                    \
        : "+f"((d)[0]), "+f"((d)[1]), "+f"((d)[2]), "+f"((d)[3])                   \
        : "r"(a0), "r"(a1), "r"(a2), "r"(a3), "r"(b0), "r"(b1))

#define LDSM_X4(r0, r1, r2, r3, addr)                                              \
    asm volatile("ldmatrix.sync.aligned.m8n8.x4.shared.b16 {%0,%1,%2,%3}, [%4];"   \
                 : "=r"(r0), "=r"(r1), "=r"(r2), "=r"(r3) : "r"(addr))

#define LDSM_X4T(r0, r1, r2, r3, addr)                                             \
    asm volatile("ldmatrix.sync.aligned.m8n8.x4.trans.shared.b16 {%0,%1,%2,%3}, [%4];" \
                 : "=r"(r0), "=r"(r1), "=r"(r2), "=r"(r3) : "r"(addr))

#define CP16(dst, src) asm volatile("cp.async.cg.shared.global [%0], [%1], 16;" :: "r"(dst), "l"(src) : "memory")
#define CP_COMMIT()    asm volatile("cp.async.commit_group;" ::: "memory")

// ---------------- Stage A1: gram partials via tensor cores (split-bf16) --------
// grid (16, 8). Each CTA: 2 column-phases of 128, accumulated in registers.
#define GROWS 144
__global__ void __launch_bounds__(256) k_gram(const float* __restrict__ cnn,
                                              const float* __restrict__ vit) {
    int chunk = blockIdx.x, img = blockIdx.y;
    const float* x = (img < BB) ? (cnn + img * CC * NN) : (vit + (img - BB) * CC * NN);
    __shared__ __align__(16) __nv_bfloat16 xh[CC][GROWS];
    __shared__ __align__(16) __nv_bfloat16 xl[CC][GROWS];
    int tid = threadIdx.x;
    int w = tid >> 5, lane = tid & 31;
    int g = lane >> 2, tp = lane & 3;
    int mi = w & 3, nh = w >> 2;
    int m0 = mi * 16, cj0 = nh * 32;
    const uint32_t BOFF2 = 16u * (GROWS * 2);

    float d[4][4];
    #pragma unroll
    for (int b2 = 0; b2 < 4; b2++)
        #pragma unroll
        for (int r = 0; r < 4; r++) d[b2][r] = 0.f;

    for (int ph = 0; ph < 2; ph++) {
        int n0 = (chunk * 2 + ph) * 128;
        __syncthreads();
        for (int i = tid; i < CC * 64; i += 256) {
            int c = i >> 6, j2 = (i & 63) * 2;
            float2 v = *(const float2*)(x + c * NN + n0 + j2);
            __nv_bfloat16 h0 = __float2bfloat16(v.x);
            __nv_bfloat16 h1 = __float2bfloat16(v.y);
            __nv_bfloat16 l0 = __float2bfloat16(v.x - __bfloat162float(h0));
            __nv_bfloat16 l1 = __float2bfloat16(v.y - __bfloat162float(h1));
            *(uint32_t*)&xh[c][j2] = ((uint32_t)__bfloat16_as_ushort(h1) << 16) | __bfloat16_as_ushort(h0);
            *(uint32_t*)&xl[c][j2] = ((uint32_t)__bfloat16_as_ushort(l1) << 16) | __bfloat16_as_ushort(l0);
        }
        __syncthreads();

        uint32_t aAh = smem_u32(&xh[m0 + (lane & 15)][(lane >> 4) * 8]);
        uint32_t aAl = smem_u32(&xl[m0 + (lane & 15)][(lane >> 4) * 8]);
        uint32_t aBh = smem_u32(&xh[cj0 + ((lane >> 4) & 1) * 8 + (lane & 7)][((lane >> 3) & 1) * 8]);
        uint32_t aBl = smem_u32(&xl[cj0 + ((lane >> 4) & 1) * 8 + (lane & 7)][((lane >> 3) & 1) * 8]);

        #pragma unroll
        for (int ks = 0; ks < 8; ks++) {
            uint32_t ah0, ah1, ah2, ah3, al0, al1, al2, al3;
            LDSM_X4(ah0, ah1, ah2, ah3, aAh);
            LDSM_X4(al0, al1, al2, al3, aAl);
            uint32_t bh[8], bl[8];
            LDSM_X4(bh[0], bh[1], bh[2], bh[3], aBh);
            LDSM_X4(bh[4], bh[5], bh[6], bh[7], aBh + BOFF2);
            LDSM_X4(bl[0], bl[1], bl[2], bl[3], aBl);
            LDSM_X4(bl[4], bl[5], bl[6], bl[7], aBl + BOFF2);
            aAh += 32; aAl += 32; aBh += 32; aBl += 32;
            #pragma unroll
            for (int b2 = 0; b2 < 4; b2++) {
                MMA_BF16_K16(d[b2], ah0, ah1, ah2, ah3, bh[2 * b2], bh[2 * b2 + 1]);
                MMA_BF16_K16(d[b2], ah0, ah1, ah2, ah3, bl[2 * b2], bl[2 * b2 + 1]);
                MMA_BF16_K16(d[b2], al0, al1, al2, al3, bh[2 * b2], bh[2 * b2 + 1]);
            }
        }
    }

    float* outp = g_gpart + (chunk * NIMG + img) * CC * CC;
    #pragma unroll
    for (int b2 = 0; b2 < 4; b2++) {
        int col = cj0 + b2 * 8 + 2 * tp;
        *(float2*)&outp[(m0 + g) * CC + col]     = make_float2(d[b2][0], d[b2][1]);
        *(float2*)&outp[(m0 + g + 8) * CC + col] = make_float2(d[b2][2], d[b2][3]);
    }
}

// ---------------- Stage A2: reduce + softmax + eff-weight compose -> bf16 ------
__global__ void k_prep(const float* __restrict__ Wq, const float* __restrict__ Wk,
                       const float* __restrict__ Wv,
                       const float* __restrict__ gcnn, const float* __restrict__ gvit) {
    int img = blockIdx.x;
    int tid = threadIdx.x;
    __shared__ __align__(16) float As[CC * CC];
    __shared__ __align__(16) float Wvs[CC * 68];
    __shared__ float Wqs[CC * C8V];

    for (int p = tid; p < CC * CC; p += 256) {
        float s = 0.f;
        #pragma unroll
        for (int ch = 0; ch < NCHUNK; ch++)
            s += g_gpart[(ch * NIMG + img) * CC * CC + p];
        As[p] = s;
    }
    __syncthreads();

    {
        int r = tid >> 2, l4 = tid & 3;
        float m = -1e30f;
        for (int d = l4; d < CC; d += 4) m = fmaxf(m, -As[r * CC + d]);
        m = fmaxf(m, __shfl_xor_sync(0xffffffffu, m, 1));
        m = fmaxf(m, __shfl_xor_sync(0xffffffffu, m, 2));
        float s = 0.f;
        for (int d = l4; d < CC; d += 4) s += __expf(-As[r * CC + d] - m);
        s += __shfl_xor_sync(0xffffffffu, s, 1);
        s += __shfl_xor_sync(0xffffffffu, s, 2);
        float inv = 1.f / s;
        for (int d = l4; d < CC; d += 4)
            As[r * CC + d] = __expf(-As[r * CC + d] - m) * inv;
    }

    const float* Wsm = (img < BB) ? Wq : Wk;
    for (int i = tid; i < C8V * CC; i += 256)
        Wqs[(i & 63) * C8V + (i >> 6)] = Wsm[i];
    if (img >= BB) {
        for (int i = tid; i < CC * CC; i += 256)
            Wvs[(i & 63) * 68 + (i >> 6)] = Wv[i];
    }
    __syncthreads();

    if (img < BB) {
        float g = gcnn[0];
        for (int p = tid; p < CC * C8V; p += 256) {
            int d = p >> 3, o = p & 7;
            float s = 0.f;
            #pragma unroll 4
            for (int c = 0; c < CC; c++) s += Wqs[c * C8V + o] * As[c * CC + d];
            g_Wqkb[(img * CC + d) * 16 + o] =
                __float2bfloat16((Wqs[d * C8V + o] + g * s) * RLN2);
        }
    } else {
        int b = img - BB;
        float g = gvit[0];
        for (int p = tid; p < CC * C8V; p += 256) {
            int d = p >> 3, o = p & 7;
            float s = 0.f;
            #pragma unroll 4
            for (int c = 0; c < CC; c++) s += Wqs[c * C8V + o] * As[c * CC + d];
            g_Wqkb[(b * CC + d) * 16 + 8 + o] = __float2bfloat16(Wqs[d * C8V + o] + g * s);
        }
        int tx = tid & 15, ty = tid >> 4;
        int o0 = tx * 4, d0 = ty * 4;
        float acc[4][4];
        #pragma unroll
        for (int i = 0; i < 4; i++)
            #pragma unroll
            for (int j = 0; j < 4; j++) acc[i][j] = 0.f;
        for (int c = 0; c < CC; c++) {
            float4 a = *(const float4*)&As[c * CC + d0];
            float4 wv = *(const float4*)&Wvs[c * 68 + o0];
            float ar[4] = {a.x, a.y, a.z, a.w};
            float wr[4] = {wv.x, wv.y, wv.z, wv.w};
            #pragma unroll
            for (int i = 0; i < 4; i++)
                #pragma unroll
                for (int j = 0; j < 4; j++) acc[i][j] += ar[i] * wr[j];
        }
        #pragma unroll
        for (int i = 0; i < 4; i++) {
            float4 wd = *(const float4*)&Wvs[(d0 + i) * 68 + o0];
            __nv_bfloat16* dst = g_Wvb + (b * CC + d0 + i) * CC + o0;
            dst[0] = __float2bfloat16(wd.x + g * acc[i][0]);
            dst[1] = __float2bfloat16(wd.y + g * acc[i][1]);
            dst[2] = __float2bfloat16(wd.z + g * acc[i][2]);
            dst[3] = __float2bfloat16(wd.w + g * acc[i][3]);
        }
    }
}

// ---------------- Stage B: tensor-core fused q/k/v projections -----------------
#define XROWS 136
__global__ void __launch_bounds__(256) k_qkv(const float* __restrict__ cnn,
                                             const float* __restrict__ vit,
                                             const float* __restrict__ bq,
                                             const float* __restrict__ bk,
                                             const float* __restrict__ bv) {
    int chunk = blockIdx.x, b = blockIdx.y;
    int tid = threadIdx.x;
    int n0 = chunk * 128;

    __shared__ __align__(16) __nv_bfloat16 xc[CC][XROWS];
    __shared__ __align__(16) __nv_bfloat16 xv[CC][XROWS];
    __shared__ __align__(16) __nv_bfloat16 Wvs[CC][72];
    __shared__ __align__(16) __nv_bfloat16 Wqks[CC][24];

    const float* pc = cnn + (size_t)b * CC * NN;
    const float* pv = vit + (size_t)b * CC * NN;
    for (int i = tid; i < CC * 64; i += 256) {
        int c = i >> 6, j2 = (i & 63) * 2;
        float2 vc = *(const float2*)(pc + c * NN + n0 + j2);
        float2 vv = *(const float2*)(pv + c * NN + n0 + j2);
        *(uint32_t*)&xc[c][j2] = ((uint32_t)__bfloat16_as_ushort(__float2bfloat16(vc.y)) << 16)
                               | __bfloat16_as_ushort(__float2bfloat16(vc.x));
        *(uint32_t*)&xv[c][j2] = ((uint32_t)__bfloat16_as_ushort(__float2bfloat16(vv.y)) << 16)
                               | __bfloat16_as_ushort(__float2bfloat16(vv.x));
    }
    // bf16 weights: straight copies
    for (int i = tid; i < CC * 8; i += 256) {          // Wv: 8 uint4-pairs per c? -> 8B chunks
        int c = i >> 3, o8 = (i & 7) * 8;
        *(uint4*)&Wvs[c][o8] = *(const uint4*)(g_Wvb + (b * CC + c) * CC + o8);
    }
    for (int i = tid; i < CC * 2; i += 256) {          // Wqk: 16 bf16 per c = 2 x 16B
        int c = i >> 1, o8 = (i & 1) * 8;
        *(uint4*)&Wqks[c][o8] = *(const uint4*)(g_Wqkb + (b * CC + c) * 16 + o8);
    }
    __syncthreads();

    int w = tid >> 5, lane = tid & 31;
    int g = lane >> 2, tp = lane & 3;
    int m0 = w * 16;

    uint32_t aC = smem_u32(&xc[(lane >> 4) * 8 + (lane & 7)][m0 + ((lane >> 3) & 1) * 8]);
    uint32_t aV = smem_u32(&xv[(lane >> 4) * 8 + (lane & 7)][m0 + ((lane >> 3) & 1) * 8]);
    uint32_t aWv  = smem_u32(&Wvs[((lane >> 3) & 1) * 8 + (lane & 7)][(lane >> 4) * 8]);
    uint32_t aWqk = smem_u32(&Wqks[((lane >> 3) & 1) * 8 + (lane & 7)][(lane >> 4) * 8]);

    float dv[8][4], dq[4], dk[4];
    #pragma unroll
    for (int j = 0; j < 8; j++) {
        dv[j][0] = bv[j * 8 + 2 * tp];
        dv[j][1] = bv[j * 8 + 2 * tp + 1];
        dv[j][2] = dv[j][0];
        dv[j][3] = dv[j][1];
    }
    dq[0] = bq[2 * tp] * RLN2; dq[1] = bq[2 * tp + 1] * RLN2; dq[2] = dq[0]; dq[3] = dq[1];
    dk[0] = bk[2 * tp];        dk[1] = bk[2 * tp + 1];        dk[2] = dk[0]; dk[3] = dk[1];

    #pragma unroll
    for (int ks = 0; ks < 4; ks++) {
        uint32_t ac0, ac1, ac2, ac3, av0, av1, av2, av3;
        LDSM_X4T(ac0, ac1, ac2, ac3, aC);
        LDSM_X4T(av0, av1, av2, av3, aV);
        uint32_t bwv[8][2];
        #pragma unroll
        for (int m = 0; m < 4; m++) {
            LDSM_X4T(bwv[2 * m][0], bwv[2 * m][1], bwv[2 * m + 1][0], bwv[2 * m + 1][1],
                     aWv + m * 32);
        }
        uint32_t bq0, bq1, bk0, bk1;
        LDSM_X4T(bq0, bq1, bk0, bk1, aWqk);
        aC += 16u * (XROWS * 2); aV += 16u * (XROWS * 2);
        aWv += 16u * (72 * 2);   aWqk += 16u * (24 * 2);

        #pragma unroll
        for (int j = 0; j < 8; j++)
            MMA_BF16_K16(dv[j], av0, av1, av2, av3, bwv[j][0], bwv[j][1]);
        MMA_BF16_K16(dq, ac0, ac1, ac2, ac3, bq0, bq1);
        MMA_BF16_K16(dk, av0, av1, av2, av3, bk0, bk1);
    }

    int ng0 = n0 + m0 + g, ng1 = ng0 + 8;
    __half* vd0 = g_v + ((size_t)(b * NN + ng0)) * CC + 2 * tp;
    __half* vd1 = g_v + ((size_t)(b * NN + ng1)) * CC + 2 * tp;
    #pragma unroll
    for (int j = 0; j < 8; j++) {
        uint32_t u0, u1;
        asm("cvt.rn.f16x2.f32 %0, %1, %2;" : "=r"(u0) : "f"(dv[j][1]), "f"(dv[j][0]));
        asm("cvt.rn.f16x2.f32 %0, %1, %2;" : "=r"(u1) : "f"(dv[j][3]), "f"(dv[j][2]));
        *(uint32_t*)(vd0 + j * 8) = u0;
        *(uint32_t*)(vd1 + j * 8) = u1;
    }
    uint32_t uq0, uq1, uk0, uk1;
    asm("cvt.rn.bf16x2.f32 %0, %1, %2;" : "=r"(uq0) : "f"(dq[1]), "f"(dq[0]));
    asm("cvt.rn.bf16x2.f32 %0, %1, %2;" : "=r"(uq1) : "f"(dq[3]), "f"(dq[2]));
    asm("cvt.rn.bf16x2.f32 %0, %1, %2;" : "=r"(uk0) : "f"(dk[1]), "f"(dk[0]));
    asm("cvt.rn.bf16x2.f32 %0, %1, %2;" : "=r"(uk1) : "f"(dk[3]), "f"(dk[2]));
    *(uint32_t*)(g_qb + ((size_t)(b * NN + ng0)) * 8 + 2 * tp) = uq0;
    *(uint32_t*)(g_qb + ((size_t)(b * NN + ng1)) * 8 + 2 * tp) = uq1;
    *(uint32_t*)(g_kb + ((size_t)(b * NN + ng0)) * 8 + 2 * tp) = uk0;
    *(uint32_t*)(g_kb + ((size_t)(b * NN + ng1)) * 8 + 2 * tp) = uk1;
}

// ---------------- Stage C: mma attention (R12 best config, unchanged) ----------
__global__ void __launch_bounds__(256, 2) k_attn() {
    int qt = blockIdx.x, b = blockIdx.y, sp = blockIdx.z;
    int tid = threadIdx.x;
    int w = tid >> 5, lane = tid & 31;
    int g = lane >> 2, tp = lane & 3;
    int kbase = sp * (NN / KSPL);

    __shared__ __align__(16) __nv_bfloat16 Ks[2][128][8];
    __shared__ __align__(16) __half        Vs[2][128][72];

    for (int i = tid; i < 2 * 128; i += 256) {
        uint4 z; z.x = 0x00003C00u; z.y = 0; z.z = 0; z.w = 0;
        *(uint4*)&Vs[i >> 7][i & 127][64] = z;
    }
    __syncthreads();

    uint32_t vbO0, vbO1;
    asm volatile("ldmatrix.sync.aligned.m8n8.x2.trans.shared.b16 {%0,%1}, [%2];"
                 : "=r"(vbO0), "=r"(vbO1) : "r"(smem_u32(&Vs[0][lane & 15][64])));

    int qrow = qt * 256 + w * 32;
    uint32_t qa[2][2];
    #pragma unroll
    for (int i = 0; i < 2; i++) {
        qa[i][0] = *(const uint32_t*)(g_qb + ((size_t)(b * NN + qrow + i * 16 + g)) * 8 + 2 * tp);
        qa[i][1] = *(const uint32_t*)(g_qb + ((size_t)(b * NN + qrow + i * 16 + g + 8)) * 8 + 2 * tp);
    }

    float d2[2][9][4];
    #pragma unroll
    for (int i = 0; i < 2; i++)
        #pragma unroll
        for (int j = 0; j < 9; j++)
            #pragma unroll
            for (int r = 0; r < 4; r++) d2[i][j][r] = 0.f;

    {
        if (tid < 128) CP16(smem_u32(&Ks[0][tid][0]), g_kb + ((size_t)(b * NN + kbase + tid)) * 8);
        #pragma unroll
        for (int i2 = 0; i2 < 4; i2++) {
            int idx = tid + i2 * 256, key = idx >> 3, c8 = (idx & 7) * 8;
            CP16(smem_u32(&Vs[0][key][c8]), g_v + ((size_t)(b * NN + kbase + key)) * CC + c8);
        }
        CP_COMMIT();
    }

    for (int t = 0; t < NTILE; t++) {
        if (t + 1 < NTILE) {
            int nb = (t + 1) & 1, k0 = kbase + (t + 1) * 128;
            if (tid < 128) CP16(smem_u32(&Ks[nb][tid][0]), g_kb + ((size_t)(b * NN + k0 + tid)) * 8);
            #pragma unroll
            for (int i2 = 0; i2 < 4; i2++) {
                int idx = tid + i2 * 256, key = idx >> 3, c8 = (idx & 7) * 8;
                CP16(smem_u32(&Vs[nb][key][c8]), g_v + ((size_t)(b * NN + k0 + key)) * CC + c8);
            }
            CP_COMMIT();
            asm volatile("cp.async.wait_group 1;" ::: "memory");
        } else {
            asm volatile("cp.async.wait_group 0;" ::: "memory");
        }
        __syncthreads();
        int bs = t & 1;

        uint32_t aK = smem_u32(&Ks[bs][lane & 15][0]);
        uint32_t aV = smem_u32(&Vs[bs][lane & 15][(lane >> 4) * 8]);
        #pragma unroll 2
        for (int kc = 0; kc < 8; kc++) {
            uint32_t kb0, kb1;
            asm volatile("ldmatrix.sync.aligned.m8n8.x2.shared.b16 {%0,%1}, [%2];"
                         : "=r"(kb0), "=r"(kb1) : "r"(aK));
            uint32_t vb[8][2];
            #pragma unroll
            for (int m = 0; m < 4; m++) {
                asm volatile("ldmatrix.sync.aligned.m8n8.x4.trans.shared.b16 {%0,%1,%2,%3}, [%4];"
                             : "=r"(vb[2 * m][0]), "=r"(vb[2 * m][1]),
                               "=r"(vb[2 * m + 1][0]), "=r"(vb[2 * m + 1][1])
                             : "r"(aV + m * 32));
            }
            aK += 16 * 16;
            aV += 16 * 144;
            #pragma unroll
            for (int i = 0; i < 2; i++) {
                float s0[4] = {0.f, 0.f, 0.f, 0.f}, s1[4] = {0.f, 0.f, 0.f, 0.f};
                MMA_BF16_K8(s0, qa[i][0], qa[i][1], kb0);
                MMA_BF16_K8(s1, qa[i][0], qa[i][1], kb1);
                uint32_t pa0, pa1, pa2, pa3;
                asm("cvt.rn.f16x2.f32 %0, %1, %2;" : "=r"(pa0) : "f"(s0[1]), "f"(s0[0]));
                asm("cvt.rn.f16x2.f32 %0, %1, %2;" : "=r"(pa1) : "f"(s0[3]), "f"(s0[2]));
                asm("cvt.rn.f16x2.f32 %0, %1, %2;" : "=r"(pa2) : "f"(s1[1]), "f"(s1[0]));
                asm("cvt.rn.f16x2.f32 %0, %1, %2;" : "=r"(pa3) : "f"(s1[3]), "f"(s1[2]));
                asm("ex2.approx.f16x2 %0, %0;" : "+r"(pa0));
                asm("ex2.approx.f16x2 %0, %0;" : "+r"(pa1));
                asm("ex2.approx.f16x2 %0, %0;" : "+r"(pa2));
                asm("ex2.approx.f16x2 %0, %0;" : "+r"(pa3));
                #pragma unroll
                for (int j = 0; j < 8; j++)
                    MMA_F16(d2[i][j], pa0, pa1, pa2, pa3, vb[j][0], vb[j][1]);
                MMA_F16(d2[i][8], pa0, pa1, pa2, pa3, vbO0, vbO1);
            }
        }
        __syncthreads();
    }

    int bs2 = b * KSPL + sp;
    uint32_t* pD = g_pDh + (size_t)bs2 * (CC / 2) * NN;
    #pragma unroll
    for (int i = 0; i < 2; i++) {
        int q0 = qrow + i * 16 + g, q1 = q0 + 8;
        if (tp == 0) {
            g_pl[(size_t)bs2 * NN + q0] = d2[i][8][0];
            g_pl[(size_t)bs2 * NN + q1] = d2[i][8][2];
        }
        #pragma unroll
        for (int j = 0; j < 8; j++) {
            int cp = j * 4 + tp;
            uint32_t w0, w1;
            asm("cvt.rn.f16x2.f32 %0, %1, %2;" : "=r"(w0) : "f"(d2[i][j][1]), "f"(d2[i][j][0]));
            asm("cvt.rn.f16x2.f32 %0, %1, %2;" : "=r"(w1) : "f"(d2[i][j][3]), "f"(d2[i][j][2]));
            pD[(size_t)cp * NN + q0] = w0;
            pD[(size_t)cp * NN + q1] = w1;
        }
    }
}

// ---------------- Stage D: combine splits + epilogue (256 CTAs) -----------------
__global__ void __launch_bounds__(256) k_comb(const float* __restrict__ gamma,
                                              const float* __restrict__ cnn,
                                              float* __restrict__ out) {
    int b = blockIdx.y;
    int q = blockIdx.x * 64 + (threadIdx.x & 63);
    int cp0 = (threadIdx.x >> 6) * 8;                  // 4 groups x 8 channel-pairs
    float l = 0.f;
    #pragma unroll
    for (int s = 0; s < KSPL; s++) l += g_pl[(size_t)(b * KSPL + s) * NN + q];
    float inv = gamma[0] / l;
    const float* cb = cnn + (size_t)b * CC * NN + q;
    float* ob = out + (size_t)b * CC * NN + q;
    #pragma unroll
    for (int i = 0; i < 8; i++) {
        int cp = cp0 + i;
        float a0 = 0.f, a1 = 0.f;
        #pragma unroll
        for (int s = 0; s < KSPL; s++) {
            uint32_t v = g_pDh[((size_t)(b * KSPL + s) * (CC / 2) + cp) * NN + q];
            float2 f = __half22float2(*reinterpret_cast<__half2*>(&v));
            a0 += f.x; a1 += f.y;
        }
        ob[(size_t)(2 * cp) * NN]     = a0 * inv + cb[(size_t)(2 * cp) * NN];
        ob[(size_t)(2 * cp + 1) * NN] = a1 * inv + cb[(size_t)(2 * cp + 1) * NN];
    }
}

// ---------------- launch ---------------------------------------------------------
extern "C" void kernel_launch(void* const* d_in, const int* in_sizes, int n_in,
                              void* d_out, int out_size) {
    const float* cnn   = (const float*)d_in[0];
    const float* vit   = (const float*)d_in[1];
    const float* Wq    = (const float*)d_in[2];
    const float* bq    = (const float*)d_in[3];
    const float* Wk    = (const float*)d_in[4];
    const float* bk    = (const float*)d_in[5];
    const float* Wv    = (const float*)d_in[6];
    const float* bv    = (const float*)d_in[7];
    const float* gamma = (const float*)d_in[8];
    const float* gcnn  = (const float*)d_in[9];
    const float* gvit  = (const float*)d_in[10];
    float* out = (float*)d_out;

    k_gram <<<dim3(NCHUNK, NIMG), 256>>>(cnn, vit);
    k_prep <<<NIMG, 256>>>(Wq, Wk, Wv, gcnn, gvit);
    k_qkv  <<<dim3(NN / 128, BB), 256>>>(cnn, vit, bq, bk, bv);
    k_attn <<<dim3(NN / 256, BB, KSPL), 256>>>();
    k_comb <<<dim3(NN / 64, BB), 256>>>(gamma, cnn, out);
}